// round 9
// baseline (speedup 1.0000x reference)
#include <cuda_runtime.h>
#include <cstdint>

static constexpr int NN = 50000;
static constexpr int EE = 600000;
static constexpr int GG = 64;
static constexpr int HH = 128;
static constexpr int TPB = 128;   // 4 warps, 32 rows each

// ---------------- scratch (no allocations allowed) ----------------
__device__ int   d_row[EE];
__device__ int   d_col[EE];
__device__ int   d_batch[NN];
__device__ int   d_is64;
__device__ float d_e_sum[NN * HH];
__device__ float d_e_aggr[NN * HH];
__device__ float d_cnt[NN];
__device__ float d_e_mean[GG * HH];
__device__ float d_v_mean[GG * HH];
__device__ int   d_start[GG + 1];
__device__ float d_W1t[HH * 4 * HH];   // [N=128][K] transposed, tf32-rounded
__device__ float d_W2t[HH * HH];
__device__ float d_V1t[HH * 3 * HH];
__device__ float d_V2t[HH * HH];

// ---------------- helpers ----------------
__device__ __forceinline__ uint32_t smem_u32(const void* p) {
    uint32_t a;
    asm("{ .reg .u64 t; cvta.to.shared.u64 t, %1; cvt.u32.u64 %0, t; }" : "=r"(a) : "l"(p));
    return a;
}
__device__ __forceinline__ void ldsm4(uint32_t* r, uint32_t addr) {
    asm volatile("ldmatrix.sync.aligned.m8n8.x4.shared.b16 {%0,%1,%2,%3}, [%4];"
        : "=r"(r[0]), "=r"(r[1]), "=r"(r[2]), "=r"(r[3]) : "r"(addr));
}
__device__ __forceinline__ void mma_tf32(float* c, const uint32_t* a, uint32_t b0, uint32_t b1) {
    asm volatile("mma.sync.aligned.m16n8k8.row.col.f32.tf32.tf32.f32 "
        "{%0,%1,%2,%3}, {%4,%5,%6,%7}, {%8,%9}, {%0,%1,%2,%3};"
        : "+f"(c[0]), "+f"(c[1]), "+f"(c[2]), "+f"(c[3])
        : "r"(a[0]), "r"(a[1]), "r"(a[2]), "r"(a[3]), "r"(b0), "r"(b1));
}
__device__ __forceinline__ float tf32r(float v) {
    uint32_t r;
    asm("cvt.rna.tf32.f32 %0, %1;" : "=r"(r) : "f"(v));
    return __uint_as_float(r);
}
__device__ __forceinline__ float4 tf32r4(float4 v) {
    return make_float4(tf32r(v.x), tf32r(v.y), tf32r(v.z), tf32r(v.w));
}
__device__ __forceinline__ void cpa16(uint32_t dst, const void* src) {
    asm volatile("cp.async.cg.shared.global [%0], [%1], 16;" :: "r"(dst), "l"(src));
}
#define CP_COMMIT() asm volatile("cp.async.commit_group;" ::: "memory")
#define CP_WAIT0()  asm volatile("cp.async.wait_group 0;" ::: "memory")
__device__ __forceinline__ float softplusf(float v) {
    float t = __expf(-fabsf(v));
    return fmaxf(v, 0.0f) + __logf(1.0f + t);
}

// ---------------- small prep kernels ----------------
__global__ void detect_kernel(const int* __restrict__ ei) {
    if (threadIdx.x == 0) {
        int all0 = 1;
        for (int i = 0; i < 64; ++i)
            if (ei[2 * i + 1] != 0) { all0 = 0; break; }
        d_is64 = all0;
    }
}
__global__ void convert_kernel(const int* __restrict__ ei, const int* __restrict__ batch) {
    int i = blockIdx.x * 256 + threadIdx.x;
    int is64 = d_is64;
    if (i < EE) {
        d_row[i] = is64 ? ei[2 * i]          : ei[i];
        d_col[i] = is64 ? ei[2 * EE + 2 * i] : ei[EE + i];
    }
    if (i < NN) d_batch[i] = is64 ? batch[2 * i] : batch[i];
}
__global__ void zero_kernel() {
    int i = blockIdx.x * 256 + threadIdx.x;
    if (i < NN * HH) d_e_sum[i] = 0.0f;
    if (i < NN) d_cnt[i] = 0.0f;
}
__global__ void seg_starts_kernel() {
    int v = blockIdx.x * 256 + threadIdx.x;
    if (v >= NN) return;
    int b = d_batch[v];
    int bp = (v == 0) ? -1 : d_batch[v - 1];
    for (int g = bp + 1; g <= b; ++g) d_start[g] = v;
    if (v == NN - 1)
        for (int g = b + 1; g <= GG; ++g) d_start[g] = NN;
}
__global__ void eaggr_kernel() {
    int i = blockIdx.x * 256 + threadIdx.x;
    if (i < NN * HH) {
        float c = d_cnt[i >> 7];
        d_e_aggr[i] = d_e_sum[i] / fmaxf(c, 1.0f);
    }
}
// W [K][N] row-major -> Wt [N][K] tf32-rounded fp32
__global__ void prep_w(const float* __restrict__ W, float* __restrict__ Wt, int K, int N) {
    int i = blockIdx.x * 256 + threadIdx.x;
    if (i < K * N) {
        int k = i / N, n = i % N;
        Wt[n * K + k] = tf32r(W[i]);
    }
}

// ---------------- fused 2-layer MLP via mma.sync tf32, pipelined, 32 rows/warp ----------------
// EDGE: in = [x[row], x[col], edge_attr, u[batch[row]]] (K=512), + scatter
// NODE: in = [x, e_aggr, u[batch]]                      (K=384)
// Dynamic smem (110592 B):
//   [0]      base[128][4]                   (2048)
//   [2048]   sA[2] [128 rows][20 floats]    (2 x 10240)
//   [22528]  sB[2] [128 n   ][20 floats]    (2 x 10240)
//   [43008]  sH1 [128 rows][132 floats]     (67584)
template<int NSEG, bool EDGE>
__global__ void __launch_bounds__(TPB, 2)
mlp2_mma(const float* __restrict__ s0, const float* __restrict__ s1,
         const float* __restrict__ s2, const float* __restrict__ s3,
         const float* __restrict__ W1t, const float* __restrict__ b1,
         const float* __restrict__ W2t, const float* __restrict__ b2,
         float* __restrict__ outp, int M)
{
    extern __shared__ char sm[];
    int* base = (int*)sm;
    char* sA0 = sm + 2048;
    char* sB0 = sm + 22528;
    char* sH1 = sm + 43008;
    const uint32_t aA = smem_u32(sA0), aB = smem_u32(sB0), aH1 = smem_u32(sH1);

    const int tid = threadIdx.x;
    const int w = tid >> 5, l = tid & 31;
    const int m0 = blockIdx.x * 128;

    {
        int r = m0 + tid;
        int b0 = 0, b1_ = 0, b2_ = 0, b3_ = 0;
        if (r < M) {
            if (EDGE) {
                int row = d_row[r];
                b0 = row * HH;
                b1_ = d_col[r] * HH;
                b2_ = r * HH;
                b3_ = d_batch[row] * HH;
            } else {
                b0 = r * HH;
                b1_ = r * HH;
                b2_ = d_batch[r] * HH;
            }
        }
        base[tid * 4 + 0] = b0; base[tid * 4 + 1] = b1_;
        base[tid * 4 + 2] = b2_; base[tid * 4 + 3] = b3_;
    }
    __syncthreads();

    const int row = tid;                 // staging: one full 16-col slice per thread
    const int K1 = NSEG * 128;
    const int NCH = NSEG * 8;
    const uint32_t stg = (uint32_t)(row * 80);

    // ldmatrix lane offsets (byte strides: sA/sB rows 80B, sH1 rows 528B)
    const uint32_t aoff0 = (uint32_t)((32 * w + (l & 15)) * 80 + (l >> 4) * 16);
    const uint32_t aoff1 = aoff0 + 16 * 80;
    const uint32_t boff4 = (uint32_t)(((l & 7) + ((l >> 4) & 1) * 8) * 80 + ((l >> 3) & 1) * 16);
    const uint32_t hoff0 = (uint32_t)((32 * w + (l & 15)) * 528 + (l >> 4) * 16);
    const uint32_t hoff1 = hoff0 + 16 * 528;

    float acc[2][16][4];
    #pragma unroll
    for (int t = 0; t < 2; ++t)
        #pragma unroll
        for (int j = 0; j < 16; ++j)
            #pragma unroll
            for (int q = 0; q < 4; ++q) acc[t][j][q] = 0.0f;

    const float* sptr[4];
    sptr[0] = s0;
    sptr[1] = EDGE ? s1 : d_e_aggr;
    sptr[2] = s2;
    sptr[3] = (NSEG == 4) ? s3 : s2;

    // ---------------- layer 1 pipeline prologue ----------------
    float4 f0, f1, f2, f3;
    {   // A(0) prefetch: this thread's row, cols 0..15
        const float* ap = sptr[0] + base[row * 4 + 0];
        f0 = *(const float4*)ap;       f1 = *(const float4*)(ap + 4);
        f2 = *(const float4*)(ap + 8); f3 = *(const float4*)(ap + 12);
        // B(0) cp.async
        const float* bp = W1t + row * K1;
        cpa16(aB + stg,      bp);
        cpa16(aB + stg + 16, bp + 4);
        cpa16(aB + stg + 32, bp + 8);
        cpa16(aB + stg + 48, bp + 12);
        CP_COMMIT();
    }

    // ---------------- layer 1: chunks of k16, 1 barrier each ----------------
    for (int c = 0; c < NCH; ++c) {
        const uint32_t boffs = (uint32_t)((c & 1) * 10240);
        // stage A(c) (tf32-rounded)
        *(float4*)(sA0 + boffs + stg)      = tf32r4(f0);
        *(float4*)(sA0 + boffs + stg + 16) = tf32r4(f1);
        *(float4*)(sA0 + boffs + stg + 32) = tf32r4(f2);
        *(float4*)(sA0 + boffs + stg + 48) = tf32r4(f3);
        // prefetch A(c+1)
        {
            int cn = (c + 1 < NCH) ? c + 1 : c;
            int k0n = cn * 16;
            const float* ap = sptr[k0n >> 7] + base[row * 4 + (k0n >> 7)] + (k0n & 127);
            f0 = *(const float4*)ap;       f1 = *(const float4*)(ap + 4);
            f2 = *(const float4*)(ap + 8); f3 = *(const float4*)(ap + 12);
        }
        CP_WAIT0();           // B(c) landed
        __syncthreads();      // A(c)/B(c) visible
        // B(c+1) cp.async into the other buffer
        if (c + 1 < NCH) {
            int k0n = (c + 1) * 16;
            const float* bp = W1t + row * K1 + k0n;
            uint32_t d = aB + (boffs ^ 10240) + stg;
            cpa16(d,      bp);
            cpa16(d + 16, bp + 4);
            cpa16(d + 32, bp + 8);
            cpa16(d + 48, bp + 12);
        }
        CP_COMMIT();

        uint32_t a00[4], a01[4], a10[4], a11[4];
        ldsm4(a00, aA + boffs + aoff0);        // tile0 k8#0
        ldsm4(a01, aA + boffs + aoff0 + 32);   // tile0 k8#1
        ldsm4(a10, aA + boffs + aoff1);        // tile1 k8#0
        ldsm4(a11, aA + boffs + aoff1 + 32);   // tile1 k8#1
        #pragma unroll
        for (int p = 0; p < 8; ++p) {
            uint32_t b[4], b2[4];
            ldsm4(b,  aB + boffs + boff4 + p * 1280);        // n-tiles 2p,2p+1 k8#0
            ldsm4(b2, aB + boffs + boff4 + p * 1280 + 32);   // n-tiles 2p,2p+1 k8#1
            mma_tf32(acc[0][2 * p],     a00, b[0],  b[1]);
            mma_tf32(acc[0][2 * p + 1], a00, b[2],  b[3]);
            mma_tf32(acc[1][2 * p],     a10, b[0],  b[1]);
            mma_tf32(acc[1][2 * p + 1], a10, b[2],  b[3]);
            mma_tf32(acc[0][2 * p],     a01, b2[0], b2[1]);
            mma_tf32(acc[0][2 * p + 1], a01, b2[2], b2[3]);
            mma_tf32(acc[1][2 * p],     a11, b2[0], b2[1]);
            mma_tf32(acc[1][2 * p + 1], a11, b2[2], b2[3]);
        }
    }

    // W2(0) cp.async early (overlaps epilogue-1)
    {
        const float* bp = W2t + row * 128;
        cpa16(aB + stg,      bp);
        cpa16(aB + stg + 16, bp + 4);
        cpa16(aB + stg + 32, bp + 8);
        cpa16(aB + stg + 48, bp + 12);
        CP_COMMIT();
    }

    // ---------------- layer-1 epilogue: bias + softplus -> sH1 ----------------
    #pragma unroll
    for (int t = 0; t < 2; ++t) {
        const int r0 = 32 * w + 16 * t + (l >> 2);
        #pragma unroll
        for (int j = 0; j < 16; ++j) {
            int col = j * 8 + 2 * (l & 3);
            float bb0 = __ldg(b1 + col), bb1 = __ldg(b1 + col + 1);
            float h00 = tf32r(softplusf(acc[t][j][0] + bb0));
            float h01 = tf32r(softplusf(acc[t][j][1] + bb1));
            float h10 = tf32r(softplusf(acc[t][j][2] + bb0));
            float h11 = tf32r(softplusf(acc[t][j][3] + bb1));
            *(float2*)(sH1 + r0 * 528 + col * 4)       = make_float2(h00, h01);
            *(float2*)(sH1 + (r0 + 8) * 528 + col * 4) = make_float2(h10, h11);
            acc[t][j][0] = acc[t][j][1] = acc[t][j][2] = acc[t][j][3] = 0.0f;
        }
    }

    // ---------------- layer 2: K=128, 8 chunks, 1 barrier each ----------------
    for (int c = 0; c < 8; ++c) {
        const uint32_t boffs = (uint32_t)((c & 1) * 10240);
        CP_WAIT0();           // W2(c) landed
        __syncthreads();      // first iter also orders sH1 stores before ldsm
        if (c + 1 < 8) {
            const float* bp = W2t + row * 128 + (c + 1) * 16;
            uint32_t d = aB + (boffs ^ 10240) + stg;
            cpa16(d,      bp);
            cpa16(d + 16, bp + 4);
            cpa16(d + 32, bp + 8);
            cpa16(d + 48, bp + 12);
        }
        CP_COMMIT();

        const int k0 = c * 16;
        uint32_t a00[4], a01[4], a10[4], a11[4];
        ldsm4(a00, aH1 + hoff0 + k0 * 4);
        ldsm4(a01, aH1 + hoff0 + k0 * 4 + 32);
        ldsm4(a10, aH1 + hoff1 + k0 * 4);
        ldsm4(a11, aH1 + hoff1 + k0 * 4 + 32);
        #pragma unroll
        for (int p = 0; p < 8; ++p) {
            uint32_t b[4], b2[4];
            ldsm4(b,  aB + boffs + boff4 + p * 1280);
            ldsm4(b2, aB + boffs + boff4 + p * 1280 + 32);
            mma_tf32(acc[0][2 * p],     a00, b[0],  b[1]);
            mma_tf32(acc[0][2 * p + 1], a00, b[2],  b[3]);
            mma_tf32(acc[1][2 * p],     a10, b[0],  b[1]);
            mma_tf32(acc[1][2 * p + 1], a10, b[2],  b[3]);
            mma_tf32(acc[0][2 * p],     a01, b2[0], b2[1]);
            mma_tf32(acc[0][2 * p + 1], a01, b2[2], b2[3]);
            mma_tf32(acc[1][2 * p],     a11, b2[0], b2[1]);
            mma_tf32(acc[1][2 * p + 1], a11, b2[2], b2[3]);
        }
    }

    // ---------------- epilogue 2: bias + softplus + store (+ scatter) ----------------
    #pragma unroll
    for (int t = 0; t < 2; ++t) {
        const int r0l = 32 * w + 16 * t + (l >> 2);   // local rows r0l, r0l+8
        const int r0 = m0 + r0l;
        const int db0 = EDGE ? base[r0l * 4 + 0] : 0;
        const int db1 = EDGE ? base[(r0l + 8) * 4 + 0] : 0;
        #pragma unroll
        for (int j = 0; j < 16; ++j) {
            int col = j * 8 + 2 * (l & 3);
            float bb0 = __ldg(b2 + col), bb1 = __ldg(b2 + col + 1);
            float o00 = softplusf(acc[t][j][0] + bb0);
            float o01 = softplusf(acc[t][j][1] + bb1);
            float o10 = softplusf(acc[t][j][2] + bb0);
            float o11 = softplusf(acc[t][j][3] + bb1);
            if (r0 < M) {
                *(float2*)(outp + (size_t)r0 * HH + col) = make_float2(o00, o01);
                if (EDGE) {
                    atomicAdd(&d_e_sum[db0 + col], o00);
                    atomicAdd(&d_e_sum[db0 + col + 1], o01);
                }
            }
            if (r0 + 8 < M) {
                *(float2*)(outp + (size_t)(r0 + 8) * HH + col) = make_float2(o10, o11);
                if (EDGE) {
                    atomicAdd(&d_e_sum[db1 + col], o10);
                    atomicAdd(&d_e_sum[db1 + col + 1], o11);
                }
            }
        }
        if (EDGE && (l & 3) == 0) {
            if (r0 < M)     atomicAdd(&d_cnt[db0 >> 7], 1.0f);
            if (r0 + 8 < M) atomicAdd(&d_cnt[db1 >> 7], 1.0f);
        }
    }
}

// ---------------- per-graph reductions + global MLP ----------------
__global__ void graph_reduce_kernel(const float* __restrict__ xnew) {
    int g = blockIdx.x;
    int n = threadIdx.x;
    int s = d_start[g], e = d_start[g + 1];
    float se = 0.0f, sv = 0.0f;
    for (int v = s; v < e; ++v) {
        se += d_e_sum[v * HH + n];
        sv += xnew[(size_t)v * HH + n];
    }
    float sc = 0.0f;
    for (int v = s + n; v < e; v += HH) sc += d_cnt[v];
    __shared__ float red[HH];
    red[n] = sc;
    __syncthreads();
    for (int off = 64; off > 0; off >>= 1) {
        if (n < off) red[n] += red[n + off];
        __syncthreads();
    }
    float ec = red[0];
    d_e_mean[g * HH + n] = se / fmaxf(ec, 1.0f);
    d_v_mean[g * HH + n] = sv / fmaxf((float)(e - s), 1.0f);
}

__global__ void global_mlp_kernel(const float* __restrict__ u,
                                  const float* __restrict__ W1, const float* __restrict__ b1,
                                  const float* __restrict__ W2, const float* __restrict__ b2,
                                  float* __restrict__ out_u) {
    __shared__ float in[3 * HH];
    __shared__ float h1s[HH];
    int g = blockIdx.x, n = threadIdx.x;
    in[n]          = u[g * HH + n];
    in[HH + n]     = d_e_mean[g * HH + n];
    in[2 * HH + n] = d_v_mean[g * HH + n];
    __syncthreads();
    float a = b1[n];
    for (int k = 0; k < 3 * HH; ++k) a += in[k] * W1[k * HH + n];
    h1s[n] = softplusf(a);
    __syncthreads();
    float o = b2[n];
    for (int k = 0; k < HH; ++k) o += h1s[k] * W2[k * HH + n];
    out_u[g * HH + n] = softplusf(o);
}

// ---------------- launch ----------------
extern "C" void kernel_launch(void* const* d_in, const int* in_sizes, int n_in,
                              void* d_out, int out_size) {
    const float* x     = (const float*)d_in[0];
    const int*   ei    = (const int*)d_in[1];
    const float* ea    = (const float*)d_in[2];
    const float* u     = (const float*)d_in[3];
    const int*   batch = (const int*)d_in[4];
    const float* We1 = (const float*)d_in[5];
    const float* be1 = (const float*)d_in[6];
    const float* We2 = (const float*)d_in[7];
    const float* be2 = (const float*)d_in[8];
    const float* Wv1 = (const float*)d_in[9];
    const float* bv1 = (const float*)d_in[10];
    const float* Wv2 = (const float*)d_in[11];
    const float* bv2 = (const float*)d_in[12];
    const float* Wu1 = (const float*)d_in[13];
    const float* bu1 = (const float*)d_in[14];
    const float* Wu2 = (const float*)d_in[15];
    const float* bu2 = (const float*)d_in[16];

    float* out   = (float*)d_out;
    float* out_x = out;
    float* out_e = out + (size_t)NN * HH;
    float* out_u = out + (size_t)(NN + EE) * HH;

    float *pW1t, *pW2t, *pV1t, *pV2t;
    cudaGetSymbolAddress((void**)&pW1t, d_W1t);
    cudaGetSymbolAddress((void**)&pW2t, d_W2t);
    cudaGetSymbolAddress((void**)&pV1t, d_V1t);
    cudaGetSymbolAddress((void**)&pV2t, d_V2t);

    const int SMEM = 110592;
    cudaFuncSetAttribute(mlp2_mma<4, true>,  cudaFuncAttributeMaxDynamicSharedMemorySize, SMEM);
    cudaFuncSetAttribute(mlp2_mma<3, false>, cudaFuncAttributeMaxDynamicSharedMemorySize, SMEM);

    detect_kernel<<<1, 32>>>(ei);
    convert_kernel<<<(EE + 255) / 256, 256>>>(ei, batch);
    zero_kernel<<<(NN * HH + 255) / 256, 256>>>();
    seg_starts_kernel<<<(NN + 255) / 256, 256>>>();

    prep_w<<<(4 * HH * HH + 255) / 256, 256>>>(We1, pW1t, 4 * HH, HH);
    prep_w<<<(HH * HH + 255) / 256, 256>>>(We2, pW2t, HH, HH);
    prep_w<<<(3 * HH * HH + 255) / 256, 256>>>(Wv1, pV1t, 3 * HH, HH);
    prep_w<<<(HH * HH + 255) / 256, 256>>>(Wv2, pV2t, HH, HH);

    // edge MLP + scatter
    mlp2_mma<4, true><<<(EE + 127) / 128, TPB, SMEM>>>(
        x, x, ea, u, pW1t, be1, pW2t, be2, out_e, EE);

    eaggr_kernel<<<(NN * HH + 255) / 256, 256>>>();

    // node MLP
    mlp2_mma<3, false><<<(NN + 127) / 128, TPB, SMEM>>>(
        x, nullptr, u, nullptr, pV1t, bv1, pV2t, bv2, out_x, NN);

    graph_reduce_kernel<<<GG, HH>>>(out_x);
    global_mlp_kernel<<<GG, HH>>>(u, Wu1, bu1, Wu2, bu2, out_u);
}

// round 10
// speedup vs baseline: 1.0008x; 1.0008x over previous
#include <cuda_runtime.h>
#include <cstdint>

static constexpr int NN = 50000;
static constexpr int EE = 600000;
static constexpr int GG = 64;
static constexpr int HH = 128;
static constexpr int TPB = 128;   // 4 warps, 32 rows each

// ---------------- scratch (no allocations allowed) ----------------
__device__ int   d_row[EE];
__device__ int   d_col[EE];
__device__ int   d_batch[NN];
__device__ int   d_is64;
__device__ float d_e_sum[NN * HH];
__device__ float d_e_aggr[NN * HH];
__device__ float d_cnt[NN];
__device__ float d_e_mean[GG * HH];
__device__ float d_v_mean[GG * HH];
__device__ int   d_start[GG + 1];
__device__ float d_W1t[HH * 4 * HH];   // [N=128][K] transposed, tf32-rounded
__device__ float d_W2t[HH * HH];
__device__ float d_V1t[HH * 3 * HH];
__device__ float d_V2t[HH * HH];

// ---------------- helpers ----------------
__device__ __forceinline__ uint32_t smem_u32(const void* p) {
    uint32_t a;
    asm("{ .reg .u64 t; cvta.to.shared.u64 t, %1; cvt.u32.u64 %0, t; }" : "=r"(a) : "l"(p));
    return a;
}
__device__ __forceinline__ void ldsm4(uint32_t* r, uint32_t addr) {
    asm volatile("ldmatrix.sync.aligned.m8n8.x4.shared.b16 {%0,%1,%2,%3}, [%4];"
        : "=r"(r[0]), "=r"(r[1]), "=r"(r[2]), "=r"(r[3]) : "r"(addr));
}
__device__ __forceinline__ void mma_tf32(float* c, const uint32_t* a, uint32_t b0, uint32_t b1) {
    asm volatile("mma.sync.aligned.m16n8k8.row.col.f32.tf32.tf32.f32 "
        "{%0,%1,%2,%3}, {%4,%5,%6,%7}, {%8,%9}, {%0,%1,%2,%3};"
        : "+f"(c[0]), "+f"(c[1]), "+f"(c[2]), "+f"(c[3])
        : "r"(a[0]), "r"(a[1]), "r"(a[2]), "r"(a[3]), "r"(b0), "r"(b1));
}
__device__ __forceinline__ float tf32r(float v) {
    uint32_t r;
    asm("cvt.rna.tf32.f32 %0, %1;" : "=r"(r) : "f"(v));
    return __uint_as_float(r);
}
__device__ __forceinline__ float4 tf32r4(float4 v) {
    return make_float4(tf32r(v.x), tf32r(v.y), tf32r(v.z), tf32r(v.w));
}
__device__ __forceinline__ void cpa16(uint32_t dst, const void* src) {
    asm volatile("cp.async.cg.shared.global [%0], [%1], 16;" :: "r"(dst), "l"(src));
}
#define CP_COMMIT() asm volatile("cp.async.commit_group;" ::: "memory")
#define CP_WAIT0()  asm volatile("cp.async.wait_group 0;" ::: "memory")
__device__ __forceinline__ float softplusf(float v) {
    float t = __expf(-fabsf(v));
    return fmaxf(v, 0.0f) + __logf(1.0f + t);
}

// ---------------- small prep kernels ----------------
__global__ void detect_kernel(const int* __restrict__ ei) {
    if (threadIdx.x == 0) {
        int all0 = 1;
        for (int i = 0; i < 64; ++i)
            if (ei[2 * i + 1] != 0) { all0 = 0; break; }
        d_is64 = all0;
    }
}
__global__ void convert_kernel(const int* __restrict__ ei, const int* __restrict__ batch) {
    int i = blockIdx.x * 256 + threadIdx.x;
    int is64 = d_is64;
    if (i < EE) {
        d_row[i] = is64 ? ei[2 * i]          : ei[i];
        d_col[i] = is64 ? ei[2 * EE + 2 * i] : ei[EE + i];
    }
    if (i < NN) d_batch[i] = is64 ? batch[2 * i] : batch[i];
}
__global__ void zero_kernel() {
    int i = blockIdx.x * 256 + threadIdx.x;
    if (i < NN * HH) d_e_sum[i] = 0.0f;
    if (i < NN) d_cnt[i] = 0.0f;
}
__global__ void seg_starts_kernel() {
    int v = blockIdx.x * 256 + threadIdx.x;
    if (v >= NN) return;
    int b = d_batch[v];
    int bp = (v == 0) ? -1 : d_batch[v - 1];
    for (int g = bp + 1; g <= b; ++g) d_start[g] = v;
    if (v == NN - 1)
        for (int g = b + 1; g <= GG; ++g) d_start[g] = NN;
}
__global__ void eaggr_kernel() {
    int i = blockIdx.x * 256 + threadIdx.x;
    if (i < NN * HH) {
        float c = d_cnt[i >> 7];
        d_e_aggr[i] = d_e_sum[i] / fmaxf(c, 1.0f);
    }
}
// W [K][N] row-major -> Wt [N][K] tf32-rounded fp32
__global__ void prep_w(const float* __restrict__ W, float* __restrict__ Wt, int K, int N) {
    int i = blockIdx.x * 256 + threadIdx.x;
    if (i < K * N) {
        int k = i / N, n = i % N;
        Wt[n * K + k] = tf32r(W[i]);
    }
}

// ---------------- fused 2-layer MLP via mma.sync tf32, pipelined, 32 rows/warp ----------------
// EDGE: in = [x[row], x[col], edge_attr, u[batch[row]]] (K=512), + scatter
// NODE: in = [x, e_aggr, u[batch]]                      (K=384)
// Dynamic smem (110592 B):
//   [0]      base[128][4]                   (2048)
//   [2048]   sA[2] [128 rows][20 floats]    (2 x 10240)
//   [22528]  sB[2] [128 n   ][20 floats]    (2 x 10240)
//   [43008]  sH1 [128 rows][132 floats]     (67584)
template<int NSEG, bool EDGE>
__global__ void __launch_bounds__(TPB, 2)
mlp2_mma(const float* __restrict__ s0, const float* __restrict__ s1,
         const float* __restrict__ s2, const float* __restrict__ s3,
         const float* __restrict__ W1t, const float* __restrict__ b1,
         const float* __restrict__ W2t, const float* __restrict__ b2,
         float* __restrict__ outp, int M)
{
    extern __shared__ char sm[];
    int* base = (int*)sm;
    char* sA0 = sm + 2048;
    char* sB0 = sm + 22528;
    char* sH1 = sm + 43008;
    const uint32_t aA = smem_u32(sA0), aB = smem_u32(sB0), aH1 = smem_u32(sH1);

    const int tid = threadIdx.x;
    const int w = tid >> 5, l = tid & 31;
    const int m0 = blockIdx.x * 128;

    {
        int r = m0 + tid;
        int b0 = 0, b1_ = 0, b2_ = 0, b3_ = 0;
        if (r < M) {
            if (EDGE) {
                int row = d_row[r];
                b0 = row * HH;
                b1_ = d_col[r] * HH;
                b2_ = r * HH;
                b3_ = d_batch[row] * HH;
            } else {
                b0 = r * HH;
                b1_ = r * HH;
                b2_ = d_batch[r] * HH;
            }
        }
        base[tid * 4 + 0] = b0; base[tid * 4 + 1] = b1_;
        base[tid * 4 + 2] = b2_; base[tid * 4 + 3] = b3_;
    }
    __syncthreads();

    const int row = tid;                 // staging: one full 16-col slice per thread
    const int K1 = NSEG * 128;
    const int NCH = NSEG * 8;
    const uint32_t stg = (uint32_t)(row * 80);

    // ldmatrix lane offsets (byte strides: sA/sB rows 80B, sH1 rows 528B)
    const uint32_t aoff0 = (uint32_t)((32 * w + (l & 15)) * 80 + (l >> 4) * 16);
    const uint32_t aoff1 = aoff0 + 16 * 80;
    const uint32_t boff4 = (uint32_t)(((l & 7) + ((l >> 4) & 1) * 8) * 80 + ((l >> 3) & 1) * 16);
    const uint32_t hoff0 = (uint32_t)((32 * w + (l & 15)) * 528 + (l >> 4) * 16);
    const uint32_t hoff1 = hoff0 + 16 * 528;

    float acc[2][16][4];
    #pragma unroll
    for (int t = 0; t < 2; ++t)
        #pragma unroll
        for (int j = 0; j < 16; ++j)
            #pragma unroll
            for (int q = 0; q < 4; ++q) acc[t][j][q] = 0.0f;

    const float* sptr[4];
    sptr[0] = s0;
    sptr[1] = EDGE ? s1 : d_e_aggr;
    sptr[2] = s2;
    sptr[3] = (NSEG == 4) ? s3 : s2;

    // ---------------- layer 1 pipeline prologue ----------------
    float4 f0, f1, f2, f3;
    {   // A(0) prefetch: this thread's row, cols 0..15
        const float* ap = sptr[0] + base[row * 4 + 0];
        f0 = *(const float4*)ap;       f1 = *(const float4*)(ap + 4);
        f2 = *(const float4*)(ap + 8); f3 = *(const float4*)(ap + 12);
        // B(0) cp.async
        const float* bp = W1t + row * K1;
        cpa16(aB + stg,      bp);
        cpa16(aB + stg + 16, bp + 4);
        cpa16(aB + stg + 32, bp + 8);
        cpa16(aB + stg + 48, bp + 12);
        CP_COMMIT();
    }

    // ---------------- layer 1: chunks of k16, 1 barrier each ----------------
    for (int c = 0; c < NCH; ++c) {
        const uint32_t boffs = (uint32_t)((c & 1) * 10240);
        // stage A(c) (tf32-rounded)
        *(float4*)(sA0 + boffs + stg)      = tf32r4(f0);
        *(float4*)(sA0 + boffs + stg + 16) = tf32r4(f1);
        *(float4*)(sA0 + boffs + stg + 32) = tf32r4(f2);
        *(float4*)(sA0 + boffs + stg + 48) = tf32r4(f3);
        // prefetch A(c+1)
        {
            int cn = (c + 1 < NCH) ? c + 1 : c;
            int k0n = cn * 16;
            const float* ap = sptr[k0n >> 7] + base[row * 4 + (k0n >> 7)] + (k0n & 127);
            f0 = *(const float4*)ap;       f1 = *(const float4*)(ap + 4);
            f2 = *(const float4*)(ap + 8); f3 = *(const float4*)(ap + 12);
        }
        CP_WAIT0();           // B(c) landed
        __syncthreads();      // A(c)/B(c) visible
        // B(c+1) cp.async into the other buffer
        if (c + 1 < NCH) {
            int k0n = (c + 1) * 16;
            const float* bp = W1t + row * K1 + k0n;
            uint32_t d = aB + (boffs ^ 10240) + stg;
            cpa16(d,      bp);
            cpa16(d + 16, bp + 4);
            cpa16(d + 32, bp + 8);
            cpa16(d + 48, bp + 12);
        }
        CP_COMMIT();

        uint32_t a00[4], a01[4], a10[4], a11[4];
        ldsm4(a00, aA + boffs + aoff0);        // tile0 k8#0
        ldsm4(a01, aA + boffs + aoff0 + 32);   // tile0 k8#1
        ldsm4(a10, aA + boffs + aoff1);        // tile1 k8#0
        ldsm4(a11, aA + boffs + aoff1 + 32);   // tile1 k8#1
        #pragma unroll
        for (int p = 0; p < 8; ++p) {
            uint32_t b[4], b2[4];
            ldsm4(b,  aB + boffs + boff4 + p * 1280);        // n-tiles 2p,2p+1 k8#0
            ldsm4(b2, aB + boffs + boff4 + p * 1280 + 32);   // n-tiles 2p,2p+1 k8#1
            mma_tf32(acc[0][2 * p],     a00, b[0],  b[1]);
            mma_tf32(acc[0][2 * p + 1], a00, b[2],  b[3]);
            mma_tf32(acc[1][2 * p],     a10, b[0],  b[1]);
            mma_tf32(acc[1][2 * p + 1], a10, b[2],  b[3]);
            mma_tf32(acc[0][2 * p],     a01, b2[0], b2[1]);
            mma_tf32(acc[0][2 * p + 1], a01, b2[2], b2[3]);
            mma_tf32(acc[1][2 * p],     a11, b2[0], b2[1]);
            mma_tf32(acc[1][2 * p + 1], a11, b2[2], b2[3]);
        }
    }

    // W2(0) cp.async early (overlaps epilogue-1)
    {
        const float* bp = W2t + row * 128;
        cpa16(aB + stg,      bp);
        cpa16(aB + stg + 16, bp + 4);
        cpa16(aB + stg + 32, bp + 8);
        cpa16(aB + stg + 48, bp + 12);
        CP_COMMIT();
    }

    // ---------------- layer-1 epilogue: bias + softplus -> sH1 ----------------
    #pragma unroll
    for (int t = 0; t < 2; ++t) {
        const int r0 = 32 * w + 16 * t + (l >> 2);
        #pragma unroll
        for (int j = 0; j < 16; ++j) {
            int col = j * 8 + 2 * (l & 3);
            float bb0 = __ldg(b1 + col), bb1 = __ldg(b1 + col + 1);
            float h00 = tf32r(softplusf(acc[t][j][0] + bb0));
            float h01 = tf32r(softplusf(acc[t][j][1] + bb1));
            float h10 = tf32r(softplusf(acc[t][j][2] + bb0));
            float h11 = tf32r(softplusf(acc[t][j][3] + bb1));
            *(float2*)(sH1 + r0 * 528 + col * 4)       = make_float2(h00, h01);
            *(float2*)(sH1 + (r0 + 8) * 528 + col * 4) = make_float2(h10, h11);
            acc[t][j][0] = acc[t][j][1] = acc[t][j][2] = acc[t][j][3] = 0.0f;
        }
    }

    // ---------------- layer 2: K=128, 8 chunks, 1 barrier each ----------------
    for (int c = 0; c < 8; ++c) {
        const uint32_t boffs = (uint32_t)((c & 1) * 10240);
        CP_WAIT0();           // W2(c) landed
        __syncthreads();      // first iter also orders sH1 stores before ldsm
        if (c + 1 < 8) {
            const float* bp = W2t + row * 128 + (c + 1) * 16;
            uint32_t d = aB + (boffs ^ 10240) + stg;
            cpa16(d,      bp);
            cpa16(d + 16, bp + 4);
            cpa16(d + 32, bp + 8);
            cpa16(d + 48, bp + 12);
        }
        CP_COMMIT();

        const int k0 = c * 16;
        uint32_t a00[4], a01[4], a10[4], a11[4];
        ldsm4(a00, aH1 + hoff0 + k0 * 4);
        ldsm4(a01, aH1 + hoff0 + k0 * 4 + 32);
        ldsm4(a10, aH1 + hoff1 + k0 * 4);
        ldsm4(a11, aH1 + hoff1 + k0 * 4 + 32);
        #pragma unroll
        for (int p = 0; p < 8; ++p) {
            uint32_t b[4], b2[4];
            ldsm4(b,  aB + boffs + boff4 + p * 1280);
            ldsm4(b2, aB + boffs + boff4 + p * 1280 + 32);
            mma_tf32(acc[0][2 * p],     a00, b[0],  b[1]);
            mma_tf32(acc[0][2 * p + 1], a00, b[2],  b[3]);
            mma_tf32(acc[1][2 * p],     a10, b[0],  b[1]);
            mma_tf32(acc[1][2 * p + 1], a10, b[2],  b[3]);
            mma_tf32(acc[0][2 * p],     a01, b2[0], b2[1]);
            mma_tf32(acc[0][2 * p + 1], a01, b2[2], b2[3]);
            mma_tf32(acc[1][2 * p],     a11, b2[0], b2[1]);
            mma_tf32(acc[1][2 * p + 1], a11, b2[2], b2[3]);
        }
    }

    // ---------------- epilogue 2: bias + softplus + store (+ scatter) ----------------
    #pragma unroll
    for (int t = 0; t < 2; ++t) {
        const int r0l = 32 * w + 16 * t + (l >> 2);   // local rows r0l, r0l+8
        const int r0 = m0 + r0l;
        const int db0 = EDGE ? base[r0l * 4 + 0] : 0;
        const int db1 = EDGE ? base[(r0l + 8) * 4 + 0] : 0;
        #pragma unroll
        for (int j = 0; j < 16; ++j) {
            int col = j * 8 + 2 * (l & 3);
            float bb0 = __ldg(b2 + col), bb1 = __ldg(b2 + col + 1);
            float o00 = softplusf(acc[t][j][0] + bb0);
            float o01 = softplusf(acc[t][j][1] + bb1);
            float o10 = softplusf(acc[t][j][2] + bb0);
            float o11 = softplusf(acc[t][j][3] + bb1);
            if (r0 < M) {
                *(float2*)(outp + (size_t)r0 * HH + col) = make_float2(o00, o01);
                if (EDGE) {
                    atomicAdd(&d_e_sum[db0 + col], o00);
                    atomicAdd(&d_e_sum[db0 + col + 1], o01);
                }
            }
            if (r0 + 8 < M) {
                *(float2*)(outp + (size_t)(r0 + 8) * HH + col) = make_float2(o10, o11);
                if (EDGE) {
                    atomicAdd(&d_e_sum[db1 + col], o10);
                    atomicAdd(&d_e_sum[db1 + col + 1], o11);
                }
            }
        }
        if (EDGE && (l & 3) == 0) {
            if (r0 < M)     atomicAdd(&d_cnt[db0 >> 7], 1.0f);
            if (r0 + 8 < M) atomicAdd(&d_cnt[db1 >> 7], 1.0f);
        }
    }
}

// ---------------- per-graph reductions + global MLP ----------------
__global__ void graph_reduce_kernel(const float* __restrict__ xnew) {
    int g = blockIdx.x;
    int n = threadIdx.x;
    int s = d_start[g], e = d_start[g + 1];
    float se = 0.0f, sv = 0.0f;
    for (int v = s; v < e; ++v) {
        se += d_e_sum[v * HH + n];
        sv += xnew[(size_t)v * HH + n];
    }
    float sc = 0.0f;
    for (int v = s + n; v < e; v += HH) sc += d_cnt[v];
    __shared__ float red[HH];
    red[n] = sc;
    __syncthreads();
    for (int off = 64; off > 0; off >>= 1) {
        if (n < off) red[n] += red[n + off];
        __syncthreads();
    }
    float ec = red[0];
    d_e_mean[g * HH + n] = se / fmaxf(ec, 1.0f);
    d_v_mean[g * HH + n] = sv / fmaxf((float)(e - s), 1.0f);
}

__global__ void global_mlp_kernel(const float* __restrict__ u,
                                  const float* __restrict__ W1, const float* __restrict__ b1,
                                  const float* __restrict__ W2, const float* __restrict__ b2,
                                  float* __restrict__ out_u) {
    __shared__ float in[3 * HH];
    __shared__ float h1s[HH];
    int g = blockIdx.x, n = threadIdx.x;
    in[n]          = u[g * HH + n];
    in[HH + n]     = d_e_mean[g * HH + n];
    in[2 * HH + n] = d_v_mean[g * HH + n];
    __syncthreads();
    float a = b1[n];
    for (int k = 0; k < 3 * HH; ++k) a += in[k] * W1[k * HH + n];
    h1s[n] = softplusf(a);
    __syncthreads();
    float o = b2[n];
    for (int k = 0; k < HH; ++k) o += h1s[k] * W2[k * HH + n];
    out_u[g * HH + n] = softplusf(o);
}

// ---------------- launch ----------------
extern "C" void kernel_launch(void* const* d_in, const int* in_sizes, int n_in,
                              void* d_out, int out_size) {
    const float* x     = (const float*)d_in[0];
    const int*   ei    = (const int*)d_in[1];
    const float* ea    = (const float*)d_in[2];
    const float* u     = (const float*)d_in[3];
    const int*   batch = (const int*)d_in[4];
    const float* We1 = (const float*)d_in[5];
    const float* be1 = (const float*)d_in[6];
    const float* We2 = (const float*)d_in[7];
    const float* be2 = (const float*)d_in[8];
    const float* Wv1 = (const float*)d_in[9];
    const float* bv1 = (const float*)d_in[10];
    const float* Wv2 = (const float*)d_in[11];
    const float* bv2 = (const float*)d_in[12];
    const float* Wu1 = (const float*)d_in[13];
    const float* bu1 = (const float*)d_in[14];
    const float* Wu2 = (const float*)d_in[15];
    const float* bu2 = (const float*)d_in[16];

    float* out   = (float*)d_out;
    float* out_x = out;
    float* out_e = out + (size_t)NN * HH;
    float* out_u = out + (size_t)(NN + EE) * HH;

    float *pW1t, *pW2t, *pV1t, *pV2t;
    cudaGetSymbolAddress((void**)&pW1t, d_W1t);
    cudaGetSymbolAddress((void**)&pW2t, d_W2t);
    cudaGetSymbolAddress((void**)&pV1t, d_V1t);
    cudaGetSymbolAddress((void**)&pV2t, d_V2t);

    const int SMEM = 110592;
    cudaFuncSetAttribute(mlp2_mma<4, true>,  cudaFuncAttributeMaxDynamicSharedMemorySize, SMEM);
    cudaFuncSetAttribute(mlp2_mma<3, false>, cudaFuncAttributeMaxDynamicSharedMemorySize, SMEM);

    detect_kernel<<<1, 32>>>(ei);
    convert_kernel<<<(EE + 255) / 256, 256>>>(ei, batch);
    zero_kernel<<<(NN * HH + 255) / 256, 256>>>();
    seg_starts_kernel<<<(NN + 255) / 256, 256>>>();

    prep_w<<<(4 * HH * HH + 255) / 256, 256>>>(We1, pW1t, 4 * HH, HH);
    prep_w<<<(HH * HH + 255) / 256, 256>>>(We2, pW2t, HH, HH);
    prep_w<<<(3 * HH * HH + 255) / 256, 256>>>(Wv1, pV1t, 3 * HH, HH);
    prep_w<<<(HH * HH + 255) / 256, 256>>>(Wv2, pV2t, HH, HH);

    // edge MLP + scatter
    mlp2_mma<4, true><<<(EE + 127) / 128, TPB, SMEM>>>(
        x, x, ea, u, pW1t, be1, pW2t, be2, out_e, EE);

    eaggr_kernel<<<(NN * HH + 255) / 256, 256>>>();

    // node MLP
    mlp2_mma<3, false><<<(NN + 127) / 128, TPB, SMEM>>>(
        x, nullptr, u, nullptr, pV1t, bv1, pV2t, bv2, out_x, NN);

    graph_reduce_kernel<<<GG, HH>>>(out_x);
    global_mlp_kernel<<<GG, HH>>>(u, Wu1, bu1, Wu2, bu2, out_u);
}

// round 11
// speedup vs baseline: 1.1721x; 1.1712x over previous
#include <cuda_runtime.h>
#include <cstdint>

static constexpr int NN = 50000;
static constexpr int EE = 600000;
static constexpr int GG = 64;
static constexpr int HH = 128;
static constexpr int TPB = 256;   // 8 warps, 16 rows each (R8 config)

// ---------------- scratch (no allocations allowed) ----------------
__device__ int   d_row[EE];
__device__ int   d_col[EE];
__device__ int   d_batch[NN];
__device__ int   d_is64;
__device__ float d_e_sum[NN * HH];
__device__ float d_cnt[NN];
__device__ float d_e_mean[GG * HH];   // used as SUM accumulators
__device__ float d_v_mean[GG * HH];   // used as SUM accumulators
__device__ float d_gecnt[GG];         // per-graph edge-count sums
__device__ int   d_start[GG + 1];
__device__ float d_W1t[HH * 4 * HH];  // [N=128][K] transposed, tf32-rounded
__device__ float d_W2t[HH * HH];
__device__ float d_V1t[HH * 3 * HH];
__device__ float d_V2t[HH * HH];

// ---------------- helpers ----------------
__device__ __forceinline__ uint32_t smem_u32(const void* p) {
    uint32_t a;
    asm("{ .reg .u64 t; cvta.to.shared.u64 t, %1; cvt.u32.u64 %0, t; }" : "=r"(a) : "l"(p));
    return a;
}
__device__ __forceinline__ void ldsm4(uint32_t* r, uint32_t addr) {
    asm volatile("ldmatrix.sync.aligned.m8n8.x4.shared.b16 {%0,%1,%2,%3}, [%4];"
        : "=r"(r[0]), "=r"(r[1]), "=r"(r[2]), "=r"(r[3]) : "r"(addr));
}
__device__ __forceinline__ void mma_tf32(float* c, const uint32_t* a, uint32_t b0, uint32_t b1) {
    asm volatile("mma.sync.aligned.m16n8k8.row.col.f32.tf32.tf32.f32 "
        "{%0,%1,%2,%3}, {%4,%5,%6,%7}, {%8,%9}, {%0,%1,%2,%3};"
        : "+f"(c[0]), "+f"(c[1]), "+f"(c[2]), "+f"(c[3])
        : "r"(a[0]), "r"(a[1]), "r"(a[2]), "r"(a[3]), "r"(b0), "r"(b1));
}
__device__ __forceinline__ float tf32r(float v) {
    uint32_t r;
    asm("cvt.rna.tf32.f32 %0, %1;" : "=r"(r) : "f"(v));
    return __uint_as_float(r);
}
__device__ __forceinline__ float4 tf32r4(float4 v) {
    return make_float4(tf32r(v.x), tf32r(v.y), tf32r(v.z), tf32r(v.w));
}
__device__ __forceinline__ void cpa16(uint32_t dst, const void* src) {
    asm volatile("cp.async.cg.shared.global [%0], [%1], 16;" :: "r"(dst), "l"(src));
}
#define CP_COMMIT() asm volatile("cp.async.commit_group;" ::: "memory")
#define CP_WAIT0()  asm volatile("cp.async.wait_group 0;" ::: "memory")
__device__ __forceinline__ float softplusf(float v) {
    float t = __expf(-fabsf(v));
    return fmaxf(v, 0.0f) + __logf(1.0f + t);
}

// ---------------- small prep kernels ----------------
__global__ void detect_kernel(const int* __restrict__ ei) {
    if (threadIdx.x == 0) {
        int all0 = 1;
        for (int i = 0; i < 64; ++i)
            if (ei[2 * i + 1] != 0) { all0 = 0; break; }
        d_is64 = all0;
    }
}
__global__ void convert_kernel(const int* __restrict__ ei, const int* __restrict__ batch) {
    int i = blockIdx.x * 256 + threadIdx.x;
    int is64 = d_is64;
    if (i < EE) {
        d_row[i] = is64 ? ei[2 * i]          : ei[i];
        d_col[i] = is64 ? ei[2 * EE + 2 * i] : ei[EE + i];
    }
    if (i < NN) d_batch[i] = is64 ? batch[2 * i] : batch[i];
}
__global__ void zero_kernel() {
    int i = blockIdx.x * 256 + threadIdx.x;
    if (i < NN * HH) d_e_sum[i] = 0.0f;
    if (i < NN) d_cnt[i] = 0.0f;
    if (i < GG * HH) { d_e_mean[i] = 0.0f; d_v_mean[i] = 0.0f; }
    if (i < GG) d_gecnt[i] = 0.0f;
}
__global__ void seg_starts_kernel() {
    int v = blockIdx.x * 256 + threadIdx.x;
    if (v >= NN) return;
    int b = d_batch[v];
    int bp = (v == 0) ? -1 : d_batch[v - 1];
    for (int g = bp + 1; g <= b; ++g) d_start[g] = v;
    if (v == NN - 1)
        for (int g = b + 1; g <= GG; ++g) d_start[g] = NN;
}
// W [K][N] row-major -> Wt [N][K] tf32-rounded fp32
__global__ void prep_w(const float* __restrict__ W, float* __restrict__ Wt, int K, int N) {
    int i = blockIdx.x * 256 + threadIdx.x;
    if (i < K * N) {
        int k = i / N, n = i % N;
        Wt[n * K + k] = tf32r(W[i]);
    }
}

// ---------------- fused 2-layer MLP via mma.sync tf32, pipelined (R8) ----------------
// EDGE: in = [x[row], x[col], edge_attr, u[batch[row]]] (K=512), + scatter
// NODE: in = [x, e_sum*rc, u[batch]]                    (K=384), rc = 1/max(cnt,1)
// Dynamic smem (111104 B):
//   [0]      base[128][4]                   (2048)
//   [2048]   sRC[128]                       (512)
//   [2560]   sA[2] [128 rows][20 floats]    (2 x 10240)
//   [23040]  sB[2] [128 n   ][20 floats]    (2 x 10240)
//   [43520]  sH1 [128 rows][132 floats]     (67584)
template<int NSEG, bool EDGE>
__global__ void __launch_bounds__(TPB, 2)
mlp2_mma(const float* __restrict__ s0, const float* __restrict__ s1,
         const float* __restrict__ s2, const float* __restrict__ s3,
         const float* __restrict__ W1t, const float* __restrict__ b1,
         const float* __restrict__ W2t, const float* __restrict__ b2,
         float* __restrict__ outp, int M)
{
    extern __shared__ char sm[];
    int* base = (int*)sm;
    float* sRC = (float*)(sm + 2048);
    char* sA0 = sm + 2560;
    char* sB0 = sm + 23040;
    char* sH1 = sm + 43520;
    const uint32_t aA = smem_u32(sA0), aB = smem_u32(sB0), aH1 = smem_u32(sH1);

    const int tid = threadIdx.x;
    const int w = tid >> 5, l = tid & 31;
    const int m0 = blockIdx.x * 128;

    if (tid < 128) {
        int r = m0 + tid;
        int b0 = 0, b1_ = 0, b2_ = 0, b3_ = 0;
        float rc = 1.0f;
        if (r < M) {
            if (EDGE) {
                int row = d_row[r];
                b0 = row * HH;
                b1_ = d_col[r] * HH;
                b2_ = r * HH;
                b3_ = d_batch[row] * HH;
            } else {
                b0 = r * HH;
                b1_ = r * HH;
                b2_ = d_batch[r] * HH;
                rc = 1.0f / fmaxf(d_cnt[r], 1.0f);
            }
        }
        base[tid * 4 + 0] = b0; base[tid * 4 + 1] = b1_;
        base[tid * 4 + 2] = b2_; base[tid * 4 + 3] = b3_;
        if (!EDGE) sRC[tid] = rc;
    }
    __syncthreads();

    const int row = tid >> 1, half = tid & 1;   // staging: 8 floats per thread
    const int K1 = NSEG * 128;
    const int NCH = NSEG * 8;
    const uint32_t stg = (uint32_t)(row * 80 + half * 32);

    // ldmatrix lane offsets (byte strides: sA/sB rows 80B, sH1 rows 528B)
    const uint32_t aoffA = (uint32_t)((16 * w + (l & 15)) * 80 + (l >> 4) * 16);
    const uint32_t boff4 = (uint32_t)(((l & 7) + ((l >> 4) & 1) * 8) * 80 + ((l >> 3) & 1) * 16);
    const uint32_t hoffA = (uint32_t)((16 * w + (l & 15)) * 528 + (l >> 4) * 16);

    float acc[16][4];
    #pragma unroll
    for (int j = 0; j < 16; ++j)
        #pragma unroll
        for (int q = 0; q < 4; ++q) acc[j][q] = 0.0f;

    const float* sptr[4];
    sptr[0] = s0;
    sptr[1] = EDGE ? s1 : d_e_sum;
    sptr[2] = s2;
    sptr[3] = (NSEG == 4) ? s3 : s2;
    const float rcm = EDGE ? 1.0f : sRC[row];   // scale for seg 1 in NODE mode

    // ---------------- layer 1 pipeline prologue ----------------
    float4 f0, f1;
    {   // A(0) prefetch
        const float* ap = sptr[0] + base[row * 4 + 0] + half * 8;
        f0 = *(const float4*)ap;
        f1 = *(const float4*)(ap + 4);
        // B(0) cp.async
        const float* bp = W1t + row * K1 + half * 8;
        cpa16(aB + stg, bp);
        cpa16(aB + stg + 16, bp + 4);
        CP_COMMIT();
    }

    int segc = 0;   // seg of chunk c (chunk 0 -> seg 0)
    // ---------------- layer 1: chunks of k16, 1 barrier each ----------------
    for (int c = 0; c < NCH; ++c) {
        const uint32_t boffs = (uint32_t)((c & 1) * 10240);
        // stage A(c) (tf32-rounded; seg-1 NODE rows scaled by 1/cnt)
        float sc = (!EDGE && segc == 1) ? rcm : 1.0f;
        *(float4*)(sA0 + boffs + stg)      = tf32r4(make_float4(f0.x * sc, f0.y * sc, f0.z * sc, f0.w * sc));
        *(float4*)(sA0 + boffs + stg + 16) = tf32r4(make_float4(f1.x * sc, f1.y * sc, f1.z * sc, f1.w * sc));
        // prefetch A(c+1)
        {
            int cn = (c + 1 < NCH) ? c + 1 : c;
            int k0n = cn * 16;
            segc = k0n >> 7;
            const float* ap = sptr[segc] + base[row * 4 + segc] + (k0n & 127) + half * 8;
            f0 = *(const float4*)ap;
            f1 = *(const float4*)(ap + 4);
        }
        CP_WAIT0();           // B(c) landed
        __syncthreads();      // A(c)/B(c) visible
        if (c + 1 < NCH) {
            int k0n = (c + 1) * 16;
            const float* bp = W1t + row * K1 + k0n + half * 8;
            cpa16(aB + (boffs ^ 10240) + stg, bp);
            cpa16(aB + (boffs ^ 10240) + stg + 16, bp + 4);
        }
        CP_COMMIT();

        uint32_t a0[4], a1[4];
        ldsm4(a0, aA + boffs + aoffA);
        ldsm4(a1, aA + boffs + aoffA + 32);
        #pragma unroll
        for (int p = 0; p < 8; ++p) {
            uint32_t b[4], b2[4];
            ldsm4(b,  aB + boffs + boff4 + p * 1280);
            ldsm4(b2, aB + boffs + boff4 + p * 1280 + 32);
            mma_tf32(acc[2 * p],     a0, b[0],  b[1]);
            mma_tf32(acc[2 * p + 1], a0, b[2],  b[3]);
            mma_tf32(acc[2 * p],     a1, b2[0], b2[1]);
            mma_tf32(acc[2 * p + 1], a1, b2[2], b2[3]);
        }
    }

    // W2(0) cp.async early (overlaps epilogue-1)
    {
        const float* bp = W2t + row * 128 + half * 8;
        cpa16(aB + stg, bp);
        cpa16(aB + stg + 16, bp + 4);
        CP_COMMIT();
    }

    // ---------------- layer-1 epilogue: bias + softplus -> sH1 ----------------
    {
        const int r0 = 16 * w + (l >> 2);
        #pragma unroll
        for (int j = 0; j < 16; ++j) {
            int col = j * 8 + 2 * (l & 3);
            float bb0 = __ldg(b1 + col), bb1 = __ldg(b1 + col + 1);
            float h00 = tf32r(softplusf(acc[j][0] + bb0));
            float h01 = tf32r(softplusf(acc[j][1] + bb1));
            float h10 = tf32r(softplusf(acc[j][2] + bb0));
            float h11 = tf32r(softplusf(acc[j][3] + bb1));
            *(float2*)(sH1 + r0 * 528 + col * 4)       = make_float2(h00, h01);
            *(float2*)(sH1 + (r0 + 8) * 528 + col * 4) = make_float2(h10, h11);
            acc[j][0] = acc[j][1] = acc[j][2] = acc[j][3] = 0.0f;
        }
    }

    // ---------------- layer 2: K=128, 8 chunks, 1 barrier each ----------------
    for (int c = 0; c < 8; ++c) {
        const uint32_t boffs = (uint32_t)((c & 1) * 10240);
        CP_WAIT0();           // W2(c) landed
        __syncthreads();      // first iter also orders sH1 stores before ldsm
        if (c + 1 < 8) {
            const float* bp = W2t + row * 128 + (c + 1) * 16 + half * 8;
            cpa16(aB + (boffs ^ 10240) + stg, bp);
            cpa16(aB + (boffs ^ 10240) + stg + 16, bp + 4);
        }
        CP_COMMIT();

        const int k0 = c * 16;
        uint32_t a0[4], a1[4];
        ldsm4(a0, aH1 + hoffA + k0 * 4);
        ldsm4(a1, aH1 + hoffA + k0 * 4 + 32);
        #pragma unroll
        for (int p = 0; p < 8; ++p) {
            uint32_t b[4], b2[4];
            ldsm4(b,  aB + boffs + boff4 + p * 1280);
            ldsm4(b2, aB + boffs + boff4 + p * 1280 + 32);
            mma_tf32(acc[2 * p],     a0, b[0],  b[1]);
            mma_tf32(acc[2 * p + 1], a0, b[2],  b[3]);
            mma_tf32(acc[2 * p],     a1, b2[0], b2[1]);
            mma_tf32(acc[2 * p + 1], a1, b2[2], b2[3]);
        }
    }

    // ---------------- epilogue 2: bias + softplus + store (+ scatter) ----------------
    {
        const int r0l = 16 * w + (l >> 2);
        const int r0 = m0 + r0l;
        const int db0 = EDGE ? base[r0l * 4 + 0] : 0;
        const int db1 = EDGE ? base[(r0l + 8) * 4 + 0] : 0;
        #pragma unroll
        for (int j = 0; j < 16; ++j) {
            int col = j * 8 + 2 * (l & 3);
            float bb0 = __ldg(b2 + col), bb1 = __ldg(b2 + col + 1);
            float o00 = softplusf(acc[j][0] + bb0);
            float o01 = softplusf(acc[j][1] + bb1);
            float o10 = softplusf(acc[j][2] + bb0);
            float o11 = softplusf(acc[j][3] + bb1);
            if (r0 < M) {
                *(float2*)(outp + (size_t)r0 * HH + col) = make_float2(o00, o01);
                if (EDGE) {
                    atomicAdd(&d_e_sum[db0 + col], o00);
                    atomicAdd(&d_e_sum[db0 + col + 1], o01);
                }
            }
            if (r0 + 8 < M) {
                *(float2*)(outp + (size_t)(r0 + 8) * HH + col) = make_float2(o10, o11);
                if (EDGE) {
                    atomicAdd(&d_e_sum[db1 + col], o10);
                    atomicAdd(&d_e_sum[db1 + col + 1], o11);
                }
            }
        }
        if (EDGE && (l & 3) == 0) {
            if (r0 < M)     atomicAdd(&d_cnt[db0 >> 7], 1.0f);
            if (r0 + 8 < M) atomicAdd(&d_cnt[db1 >> 7], 1.0f);
        }
    }
}

// ---------------- per-graph partial reductions (grid: GG x NSPLIT) ----------------
static constexpr int NSPLIT = 8;
__global__ void graph_partial_kernel(const float* __restrict__ xnew) {
    int g = blockIdx.x;
    int n = threadIdx.x;
    int s = d_start[g], e = d_start[g + 1];
    int len = e - s;
    int per = (len + NSPLIT - 1) / NSPLIT;
    int ls = s + blockIdx.y * per;
    int le = min(ls + per, e);
    if (ls >= le) return;
    float se = 0.0f, sv = 0.0f;
    for (int v = ls; v < le; ++v) {
        se += d_e_sum[v * HH + n];
        sv += xnew[(size_t)v * HH + n];
    }
    atomicAdd(&d_e_mean[g * HH + n], se);
    atomicAdd(&d_v_mean[g * HH + n], sv);
    // edge-count partial sum
    __shared__ float red[HH];
    float sc = 0.0f;
    for (int v = ls + n; v < le; v += HH) sc += d_cnt[v];
    red[n] = sc;
    __syncthreads();
    for (int off = 64; off > 0; off >>= 1) {
        if (n < off) red[n] += red[n + off];
        __syncthreads();
    }
    if (n == 0) atomicAdd(&d_gecnt[g], red[0]);
}

__global__ void global_mlp_kernel(const float* __restrict__ u,
                                  const float* __restrict__ W1, const float* __restrict__ b1,
                                  const float* __restrict__ W2, const float* __restrict__ b2,
                                  float* __restrict__ out_u) {
    __shared__ float in[3 * HH];
    __shared__ float h1s[HH];
    int g = blockIdx.x, n = threadIdx.x;
    float ec = fmaxf(d_gecnt[g], 1.0f);
    float vc = fmaxf((float)(d_start[g + 1] - d_start[g]), 1.0f);
    in[n]          = u[g * HH + n];
    in[HH + n]     = d_e_mean[g * HH + n] / ec;
    in[2 * HH + n] = d_v_mean[g * HH + n] / vc;
    __syncthreads();
    float a = b1[n];
    for (int k = 0; k < 3 * HH; ++k) a += in[k] * W1[k * HH + n];
    h1s[n] = softplusf(a);
    __syncthreads();
    float o = b2[n];
    for (int k = 0; k < HH; ++k) o += h1s[k] * W2[k * HH + n];
    out_u[g * HH + n] = softplusf(o);
}

// ---------------- launch ----------------
extern "C" void kernel_launch(void* const* d_in, const int* in_sizes, int n_in,
                              void* d_out, int out_size) {
    const float* x     = (const float*)d_in[0];
    const int*   ei    = (const int*)d_in[1];
    const float* ea    = (const float*)d_in[2];
    const float* u     = (const float*)d_in[3];
    const int*   batch = (const int*)d_in[4];
    const float* We1 = (const float*)d_in[5];
    const float* be1 = (const float*)d_in[6];
    const float* We2 = (const float*)d_in[7];
    const float* be2 = (const float*)d_in[8];
    const float* Wv1 = (const float*)d_in[9];
    const float* bv1 = (const float*)d_in[10];
    const float* Wv2 = (const float*)d_in[11];
    const float* bv2 = (const float*)d_in[12];
    const float* Wu1 = (const float*)d_in[13];
    const float* bu1 = (const float*)d_in[14];
    const float* Wu2 = (const float*)d_in[15];
    const float* bu2 = (const float*)d_in[16];

    float* out   = (float*)d_out;
    float* out_x = out;
    float* out_e = out + (size_t)NN * HH;
    float* out_u = out + (size_t)(NN + EE) * HH;

    float *pW1t, *pW2t, *pV1t, *pV2t;
    cudaGetSymbolAddress((void**)&pW1t, d_W1t);
    cudaGetSymbolAddress((void**)&pW2t, d_W2t);
    cudaGetSymbolAddress((void**)&pV1t, d_V1t);
    cudaGetSymbolAddress((void**)&pV2t, d_V2t);

    const int SMEM = 111104;
    cudaFuncSetAttribute(mlp2_mma<4, true>,  cudaFuncAttributeMaxDynamicSharedMemorySize, SMEM);
    cudaFuncSetAttribute(mlp2_mma<3, false>, cudaFuncAttributeMaxDynamicSharedMemorySize, SMEM);

    detect_kernel<<<1, 32>>>(ei);
    convert_kernel<<<(EE + 255) / 256, 256>>>(ei, batch);
    zero_kernel<<<(NN * HH + 255) / 256, 256>>>();
    seg_starts_kernel<<<(NN + 255) / 256, 256>>>();

    prep_w<<<(4 * HH * HH + 255) / 256, 256>>>(We1, pW1t, 4 * HH, HH);
    prep_w<<<(HH * HH + 255) / 256, 256>>>(We2, pW2t, HH, HH);
    prep_w<<<(3 * HH * HH + 255) / 256, 256>>>(Wv1, pV1t, 3 * HH, HH);
    prep_w<<<(HH * HH + 255) / 256, 256>>>(Wv2, pV2t, HH, HH);

    // edge MLP + scatter
    mlp2_mma<4, true><<<(EE + 127) / 128, TPB, SMEM>>>(
        x, x, ea, u, pW1t, be1, pW2t, be2, out_e, EE);

    // node MLP (e_aggr computed on the fly: e_sum * 1/max(cnt,1))
    mlp2_mma<3, false><<<(NN + 127) / 128, TPB, SMEM>>>(
        x, nullptr, u, nullptr, pV1t, bv1, pV2t, bv2, out_x, NN);

    // per-graph means (split partials) + global MLP
    graph_partial_kernel<<<dim3(GG, NSPLIT), HH>>>(out_x);
    global_mlp_kernel<<<GG, HH>>>(u, Wu1, bu1, Wu2, bu2, out_u);
}

// round 12
// speedup vs baseline: 1.1805x; 1.0071x over previous
#include <cuda_runtime.h>
#include <cstdint>

static constexpr int NN = 50000;
static constexpr int EE = 600000;
static constexpr int GG = 64;
static constexpr int HH = 128;
static constexpr int TPB = 256;   // 8 warps, 16 rows each

// ---------------- scratch (no allocations allowed) ----------------
__device__ int   d_row[EE];
__device__ int   d_col[EE];
__device__ int   d_batch[NN];
__device__ int   d_is64;
__device__ float d_e_sum[NN * HH];
__device__ float d_cnt[NN];
__device__ float d_e_mean[GG * HH];   // SUM accumulators
__device__ float d_v_mean[GG * HH];   // SUM accumulators
__device__ float d_gecnt[GG];
__device__ int   d_start[GG + 1];
__device__ float d_W1t[HH * 4 * HH];  // [N=128][K] transposed, tf32-rounded
__device__ float d_W2t[HH * HH];
__device__ float d_V1t[HH * 3 * HH];
__device__ float d_V2t[HH * HH];

// ---------------- helpers ----------------
__device__ __forceinline__ uint32_t smem_u32(const void* p) {
    uint32_t a;
    asm("{ .reg .u64 t; cvta.to.shared.u64 t, %1; cvt.u32.u64 %0, t; }" : "=r"(a) : "l"(p));
    return a;
}
__device__ __forceinline__ void ldsm4(uint32_t* r, uint32_t addr) {
    asm volatile("ldmatrix.sync.aligned.m8n8.x4.shared.b16 {%0,%1,%2,%3}, [%4];"
        : "=r"(r[0]), "=r"(r[1]), "=r"(r[2]), "=r"(r[3]) : "r"(addr));
}
__device__ __forceinline__ void mma_tf32(float* c, const uint32_t* a, uint32_t b0, uint32_t b1) {
    asm volatile("mma.sync.aligned.m16n8k8.row.col.f32.tf32.tf32.f32 "
        "{%0,%1,%2,%3}, {%4,%5,%6,%7}, {%8,%9}, {%0,%1,%2,%3};"
        : "+f"(c[0]), "+f"(c[1]), "+f"(c[2]), "+f"(c[3])
        : "r"(a[0]), "r"(a[1]), "r"(a[2]), "r"(a[3]), "r"(b0), "r"(b1));
}
__device__ __forceinline__ float tf32r(float v) {
    uint32_t r;
    asm("cvt.rna.tf32.f32 %0, %1;" : "=r"(r) : "f"(v));
    return __uint_as_float(r);
}
__device__ __forceinline__ float4 tf32r4s(float4 v, float s) {
    return make_float4(tf32r(v.x * s), tf32r(v.y * s), tf32r(v.z * s), tf32r(v.w * s));
}
__device__ __forceinline__ void cpa16(uint32_t dst, const void* src) {
    asm volatile("cp.async.cg.shared.global [%0], [%1], 16;" :: "r"(dst), "l"(src));
}
#define CP_COMMIT() asm volatile("cp.async.commit_group;" ::: "memory")
#define CP_WAIT0()  asm volatile("cp.async.wait_group 0;" ::: "memory")
__device__ __forceinline__ float softplusf(float v) {
    float t = __expf(-fabsf(v));
    return fmaxf(v, 0.0f) + __logf(1.0f + t);
}

// ---------------- prep kernels (fused for fewer launches) ----------------
__global__ void detect_kernel(const int* __restrict__ ei) {
    if (threadIdx.x == 0) {
        int all0 = 1;
        for (int i = 0; i < 64; ++i)
            if (ei[2 * i + 1] != 0) { all0 = 0; break; }
        d_is64 = all0;
    }
}
// convert indices + zero accumulators, one kernel (grid covers NN*HH)
__global__ void convert_zero_kernel(const int* __restrict__ ei, const int* __restrict__ batch) {
    int i = blockIdx.x * 256 + threadIdx.x;
    int is64 = d_is64;
    if (i < EE) {
        d_row[i] = is64 ? ei[2 * i]          : ei[i];
        d_col[i] = is64 ? ei[2 * EE + 2 * i] : ei[EE + i];
    }
    if (i < NN) {
        d_batch[i] = is64 ? batch[2 * i] : batch[i];
        d_cnt[i] = 0.0f;
    }
    if (i < NN * HH) d_e_sum[i] = 0.0f;
    if (i < GG * HH) { d_e_mean[i] = 0.0f; d_v_mean[i] = 0.0f; }
    if (i < GG) d_gecnt[i] = 0.0f;
}
// all 4 weight transposes+roundings in one kernel
__global__ void prep_all_kernel(const float* __restrict__ We1, const float* __restrict__ We2,
                                const float* __restrict__ Wv1, const float* __restrict__ Wv2) {
    int i = blockIdx.x * 256 + threadIdx.x;
    // We1: 4H x H
    if (i < 4 * HH * HH) {
        int k = i / HH, n = i % HH;
        d_W1t[n * (4 * HH) + k] = tf32r(We1[i]);
    }
    // Wv1: 3H x H
    if (i < 3 * HH * HH) {
        int k = i / HH, n = i % HH;
        d_V1t[n * (3 * HH) + k] = tf32r(Wv1[i]);
    }
    // We2 / Wv2: H x H
    if (i < HH * HH) {
        int k = i / HH, n = i % HH;
        d_W2t[n * HH + k] = tf32r(We2[i]);
        d_V2t[n * HH + k] = tf32r(Wv2[i]);
    }
}
__global__ void seg_starts_kernel() {
    int v = blockIdx.x * 256 + threadIdx.x;
    if (v >= NN) return;
    int b = d_batch[v];
    int bp = (v == 0) ? -1 : d_batch[v - 1];
    for (int g = bp + 1; g <= b; ++g) d_start[g] = v;
    if (v == NN - 1)
        for (int g = b + 1; g <= GG; ++g) d_start[g] = NN;
}

// ---------------- fused 2-layer MLP via mma.sync tf32, pipelined ----------------
// EDGE: in = [x[row], x[col], edge_attr, u[batch[row]]] (K=512), + scatter
// NODE: in = [x, e_sum*rc, u[batch]]                    (K=384), rc = 1/max(cnt,1)
// A prefetch is TWO chunks deep (fA/fB ping-pong, loop unrolled by 2).
// Dynamic smem (111104 B):
//   [0]      base[128][4]                   (2048)
//   [2048]   sRC[128]                       (512)
//   [2560]   sA[2] [128 rows][20 floats]    (2 x 10240)
//   [23040]  sB[2] [128 n   ][20 floats]    (2 x 10240)
//   [43520]  sH1 [128 rows][132 floats]     (67584)
template<int NSEG, bool EDGE>
__global__ void __launch_bounds__(TPB, 2)
mlp2_mma(const float* __restrict__ s0, const float* __restrict__ s1,
         const float* __restrict__ s2, const float* __restrict__ s3,
         const float* __restrict__ W1t, const float* __restrict__ b1,
         const float* __restrict__ W2t, const float* __restrict__ b2,
         float* __restrict__ outp, int M)
{
    extern __shared__ char sm[];
    int* base = (int*)sm;
    float* sRC = (float*)(sm + 2048);
    char* sA0 = sm + 2560;
    char* sB0 = sm + 23040;
    char* sH1 = sm + 43520;
    const uint32_t aA = smem_u32(sA0), aB = smem_u32(sB0), aH1 = smem_u32(sH1);

    const int tid = threadIdx.x;
    const int w = tid >> 5, l = tid & 31;
    const int m0 = blockIdx.x * 128;

    if (tid < 128) {
        int r = m0 + tid;
        int b0 = 0, b1_ = 0, b2_ = 0, b3_ = 0;
        float rc = 1.0f;
        if (r < M) {
            if (EDGE) {
                int row = d_row[r];
                b0 = row * HH;
                b1_ = d_col[r] * HH;
                b2_ = r * HH;
                b3_ = d_batch[row] * HH;
            } else {
                b0 = r * HH;
                b1_ = r * HH;
                b2_ = d_batch[r] * HH;
                rc = 1.0f / fmaxf(d_cnt[r], 1.0f);
            }
        }
        base[tid * 4 + 0] = b0; base[tid * 4 + 1] = b1_;
        base[tid * 4 + 2] = b2_; base[tid * 4 + 3] = b3_;
        if (!EDGE) sRC[tid] = rc;
    }
    __syncthreads();

    const int row = tid >> 1, half = tid & 1;
    const int K1 = NSEG * 128;
    const int NCH = NSEG * 8;                 // even
    const uint32_t stg = (uint32_t)(row * 80 + half * 32);

    const uint32_t aoffA = (uint32_t)((16 * w + (l & 15)) * 80 + (l >> 4) * 16);
    const uint32_t boff4 = (uint32_t)(((l & 7) + ((l >> 4) & 1) * 8) * 80 + ((l >> 3) & 1) * 16);
    const uint32_t hoffA = (uint32_t)((16 * w + (l & 15)) * 528 + (l >> 4) * 16);

    float acc[16][4];
    #pragma unroll
    for (int j = 0; j < 16; ++j)
        #pragma unroll
        for (int q = 0; q < 4; ++q) acc[j][q] = 0.0f;

    const float* sptr[4];
    sptr[0] = s0;
    sptr[1] = EDGE ? s1 : d_e_sum;
    sptr[2] = s2;
    sptr[3] = (NSEG == 4) ? s3 : s2;
    const float rcm = EDGE ? 1.0f : sRC[row];

    // A-load for chunk index c (clamped)
    auto loadA = [&](int c, float4& g0, float4& g1) {
        int cc = (c < NCH) ? c : NCH - 1;
        int k0 = cc * 16;
        int sg = k0 >> 7;
        const float* ap = sptr[sg] + base[row * 4 + sg] + (k0 & 127) + half * 8;
        g0 = *(const float4*)ap;
        g1 = *(const float4*)(ap + 4);
    };
    auto segscale = [&](int c) -> float {
        return (!EDGE && ((c * 16) >> 7) == 1) ? rcm : 1.0f;
    };

    // ---------------- layer 1 prologue: A 2-deep, B 1-deep ----------------
    float4 fA0, fA1, fB0, fB1;
    loadA(0, fA0, fA1);
    loadA(1, fB0, fB1);
    {
        const float* bp = W1t + row * K1 + half * 8;
        cpa16(aB + stg, bp);
        cpa16(aB + stg + 16, bp + 4);
        CP_COMMIT();
    }

    // ---------------- layer 1: unrolled by 2, 1 barrier per chunk ----------------
    #pragma unroll 1
    for (int c = 0; c < NCH; c += 2) {
        // ---- sub-iter c (buffer 0) ----
        {
            float sc = segscale(c);
            *(float4*)(sA0 + stg)      = tf32r4s(fA0, sc);
            *(float4*)(sA0 + stg + 16) = tf32r4s(fA1, sc);
            loadA(c + 2, fA0, fA1);                 // 2-deep prefetch
            CP_WAIT0();
            __syncthreads();
            {   // B(c+1) -> buffer 1
                int k0n = ((c + 1) < NCH) ? (c + 1) * 16 : c * 16;
                const float* bp = W1t + row * K1 + k0n + half * 8;
                cpa16(aB + 10240 + stg, bp);
                cpa16(aB + 10240 + stg + 16, bp + 4);
            }
            CP_COMMIT();
            uint32_t a0[4], a1[4];
            ldsm4(a0, aA + aoffA);
            ldsm4(a1, aA + aoffA + 32);
            #pragma unroll
            for (int p = 0; p < 8; ++p) {
                uint32_t b[4], b2[4];
                ldsm4(b,  aB + boff4 + p * 1280);
                ldsm4(b2, aB + boff4 + p * 1280 + 32);
                mma_tf32(acc[2 * p],     a0, b[0],  b[1]);
                mma_tf32(acc[2 * p + 1], a0, b[2],  b[3]);
                mma_tf32(acc[2 * p],     a1, b2[0], b2[1]);
                mma_tf32(acc[2 * p + 1], a1, b2[2], b2[3]);
            }
        }
        // ---- sub-iter c+1 (buffer 1) ----
        {
            float sc = segscale(c + 1);
            *(float4*)(sA0 + 10240 + stg)      = tf32r4s(fB0, sc);
            *(float4*)(sA0 + 10240 + stg + 16) = tf32r4s(fB1, sc);
            loadA(c + 3, fB0, fB1);                 // 2-deep prefetch
            CP_WAIT0();
            __syncthreads();
            if (c + 2 < NCH) {                      // B(c+2) -> buffer 0
                const float* bp = W1t + row * K1 + (c + 2) * 16 + half * 8;
                cpa16(aB + stg, bp);
                cpa16(aB + stg + 16, bp + 4);
            }
            CP_COMMIT();
            uint32_t a0[4], a1[4];
            ldsm4(a0, aA + 10240 + aoffA);
            ldsm4(a1, aA + 10240 + aoffA + 32);
            #pragma unroll
            for (int p = 0; p < 8; ++p) {
                uint32_t b[4], b2[4];
                ldsm4(b,  aB + 10240 + boff4 + p * 1280);
                ldsm4(b2, aB + 10240 + boff4 + p * 1280 + 32);
                mma_tf32(acc[2 * p],     a0, b[0],  b[1]);
                mma_tf32(acc[2 * p + 1], a0, b[2],  b[3]);
                mma_tf32(acc[2 * p],     a1, b2[0], b2[1]);
                mma_tf32(acc[2 * p + 1], a1, b2[2], b2[3]);
            }
        }
    }

    // W2(0) cp.async early (overlaps epilogue-1)
    {
        const float* bp = W2t + row * 128 + half * 8;
        cpa16(aB + stg, bp);
        cpa16(aB + stg + 16, bp + 4);
        CP_COMMIT();
    }

    // ---------------- layer-1 epilogue: bias + softplus -> sH1 ----------------
    {
        const int r0 = 16 * w + (l >> 2);
        #pragma unroll
        for (int j = 0; j < 16; ++j) {
            int col = j * 8 + 2 * (l & 3);
            float bb0 = __ldg(b1 + col), bb1 = __ldg(b1 + col + 1);
            float h00 = tf32r(softplusf(acc[j][0] + bb0));
            float h01 = tf32r(softplusf(acc[j][1] + bb1));
            float h10 = tf32r(softplusf(acc[j][2] + bb0));
            float h11 = tf32r(softplusf(acc[j][3] + bb1));
            *(float2*)(sH1 + r0 * 528 + col * 4)       = make_float2(h00, h01);
            *(float2*)(sH1 + (r0 + 8) * 528 + col * 4) = make_float2(h10, h11);
            acc[j][0] = acc[j][1] = acc[j][2] = acc[j][3] = 0.0f;
        }
    }

    // ---------------- layer 2: K=128, 8 chunks, 1 barrier each ----------------
    for (int c = 0; c < 8; ++c) {
        const uint32_t boffs = (uint32_t)((c & 1) * 10240);
        CP_WAIT0();
        __syncthreads();
        if (c + 1 < 8) {
            const float* bp = W2t + row * 128 + (c + 1) * 16 + half * 8;
            cpa16(aB + (boffs ^ 10240) + stg, bp);
            cpa16(aB + (boffs ^ 10240) + stg + 16, bp + 4);
        }
        CP_COMMIT();

        const int k0 = c * 16;
        uint32_t a0[4], a1[4];
        ldsm4(a0, aH1 + hoffA + k0 * 4);
        ldsm4(a1, aH1 + hoffA + k0 * 4 + 32);
        #pragma unroll
        for (int p = 0; p < 8; ++p) {
            uint32_t b[4], b2[4];
            ldsm4(b,  aB + boffs + boff4 + p * 1280);
            ldsm4(b2, aB + boffs + boff4 + p * 1280 + 32);
            mma_tf32(acc[2 * p],     a0, b[0],  b[1]);
            mma_tf32(acc[2 * p + 1], a0, b[2],  b[3]);
            mma_tf32(acc[2 * p],     a1, b2[0], b2[1]);
            mma_tf32(acc[2 * p + 1], a1, b2[2], b2[3]);
        }
    }

    // ---------------- epilogue 2: bias + softplus + store (+ scatter) ----------------
    {
        const int r0l = 16 * w + (l >> 2);
        const int r0 = m0 + r0l;
        const int db0 = EDGE ? base[r0l * 4 + 0] : 0;
        const int db1 = EDGE ? base[(r0l + 8) * 4 + 0] : 0;
        #pragma unroll
        for (int j = 0; j < 16; ++j) {
            int col = j * 8 + 2 * (l & 3);
            float bb0 = __ldg(b2 + col), bb1 = __ldg(b2 + col + 1);
            float o00 = softplusf(acc[j][0] + bb0);
            float o01 = softplusf(acc[j][1] + bb1);
            float o10 = softplusf(acc[j][2] + bb0);
            float o11 = softplusf(acc[j][3] + bb1);
            if (r0 < M) {
                *(float2*)(outp + (size_t)r0 * HH + col) = make_float2(o00, o01);
                if (EDGE) {
                    atomicAdd(&d_e_sum[db0 + col], o00);
                    atomicAdd(&d_e_sum[db0 + col + 1], o01);
                }
            }
            if (r0 + 8 < M) {
                *(float2*)(outp + (size_t)(r0 + 8) * HH + col) = make_float2(o10, o11);
                if (EDGE) {
                    atomicAdd(&d_e_sum[db1 + col], o10);
                    atomicAdd(&d_e_sum[db1 + col + 1], o11);
                }
            }
        }
        if (EDGE && (l & 3) == 0) {
            if (r0 < M)     atomicAdd(&d_cnt[db0 >> 7], 1.0f);
            if (r0 + 8 < M) atomicAdd(&d_cnt[db1 >> 7], 1.0f);
        }
    }
}

// ---------------- per-graph partial reductions (grid: GG x NSPLIT) ----------------
static constexpr int NSPLIT = 8;
__global__ void graph_partial_kernel(const float* __restrict__ xnew) {
    int g = blockIdx.x;
    int n = threadIdx.x;
    int s = d_start[g], e = d_start[g + 1];
    int len = e - s;
    int per = (len + NSPLIT - 1) / NSPLIT;
    int ls = s + blockIdx.y * per;
    int le = min(ls + per, e);
    if (ls >= le) return;
    float se = 0.0f, sv = 0.0f;
    for (int v = ls; v < le; ++v) {
        se += d_e_sum[v * HH + n];
        sv += xnew[(size_t)v * HH + n];
    }
    atomicAdd(&d_e_mean[g * HH + n], se);
    atomicAdd(&d_v_mean[g * HH + n], sv);
    __shared__ float red[HH];
    float sc = 0.0f;
    for (int v = ls + n; v < le; v += HH) sc += d_cnt[v];
    red[n] = sc;
    __syncthreads();
    for (int off = 64; off > 0; off >>= 1) {
        if (n < off) red[n] += red[n + off];
        __syncthreads();
    }
    if (n == 0) atomicAdd(&d_gecnt[g], red[0]);
}

__global__ void global_mlp_kernel(const float* __restrict__ u,
                                  const float* __restrict__ W1, const float* __restrict__ b1,
                                  const float* __restrict__ W2, const float* __restrict__ b2,
                                  float* __restrict__ out_u) {
    __shared__ float in[3 * HH];
    __shared__ float h1s[HH];
    int g = blockIdx.x, n = threadIdx.x;
    float ec = fmaxf(d_gecnt[g], 1.0f);
    float vc = fmaxf((float)(d_start[g + 1] - d_start[g]), 1.0f);
    in[n]          = u[g * HH + n];
    in[HH + n]     = d_e_mean[g * HH + n] / ec;
    in[2 * HH + n] = d_v_mean[g * HH + n] / vc;
    __syncthreads();
    float a = b1[n];
    for (int k = 0; k < 3 * HH; ++k) a += in[k] * W1[k * HH + n];
    h1s[n] = softplusf(a);
    __syncthreads();
    float o = b2[n];
    for (int k = 0; k < HH; ++k) o += h1s[k] * W2[k * HH + n];
    out_u[g * HH + n] = softplusf(o);
}

// ---------------- launch ----------------
extern "C" void kernel_launch(void* const* d_in, const int* in_sizes, int n_in,
                              void* d_out, int out_size) {
    const float* x     = (const float*)d_in[0];
    const int*   ei    = (const int*)d_in[1];
    const float* ea    = (const float*)d_in[2];
    const float* u     = (const float*)d_in[3];
    const int*   batch = (const int*)d_in[4];
    const float* We1 = (const float*)d_in[5];
    const float* be1 = (const float*)d_in[6];
    const float* We2 = (const float*)d_in[7];
    const float* be2 = (const float*)d_in[8];
    const float* Wv1 = (const float*)d_in[9];
    const float* bv1 = (const float*)d_in[10];
    const float* Wv2 = (const float*)d_in[11];
    const float* bv2 = (const float*)d_in[12];
    const float* Wu1 = (const float*)d_in[13];
    const float* bu1 = (const float*)d_in[14];
    const float* Wu2 = (const float*)d_in[15];
    const float* bu2 = (const float*)d_in[16];

    float* out   = (float*)d_out;
    float* out_x = out;
    float* out_e = out + (size_t)NN * HH;
    float* out_u = out + (size_t)(NN + EE) * HH;

    float *pW1t, *pW2t, *pV1t, *pV2t;
    cudaGetSymbolAddress((void**)&pW1t, d_W1t);
    cudaGetSymbolAddress((void**)&pW2t, d_W2t);
    cudaGetSymbolAddress((void**)&pV1t, d_V1t);
    cudaGetSymbolAddress((void**)&pV2t, d_V2t);

    const int SMEM = 111104;
    cudaFuncSetAttribute(mlp2_mma<4, true>,  cudaFuncAttributeMaxDynamicSharedMemorySize, SMEM);
    cudaFuncSetAttribute(mlp2_mma<3, false>, cudaFuncAttributeMaxDynamicSharedMemorySize, SMEM);

    // launch order chosen so the edge MLP is the 4th launch (ncu capture window)
    detect_kernel<<<1, 32>>>(ei);
    convert_zero_kernel<<<(NN * HH + 255) / 256, 256>>>(ei, batch);
    prep_all_kernel<<<(4 * HH * HH + 255) / 256, 256>>>(We1, We2, Wv1, Wv2);

    // edge MLP + scatter
    mlp2_mma<4, true><<<(EE + 127) / 128, TPB, SMEM>>>(
        x, x, ea, u, pW1t, be1, pW2t, be2, out_e, EE);

    // node MLP (e_aggr on the fly: e_sum * 1/max(cnt,1))
    mlp2_mma<3, false><<<(NN + 127) / 128, TPB, SMEM>>>(
        x, nullptr, u, nullptr, pV1t, bv1, pV2t, bv2, out_x, NN);

    seg_starts_kernel<<<(NN + 255) / 256, 256>>>();
    graph_partial_kernel<<<dim3(GG, NSPLIT), HH>>>(out_x);
    global_mlp_kernel<<<GG, HH>>>(u, Wu1, bu1, Wu2, bu2, out_u);
}

// round 13
// speedup vs baseline: 1.3396x; 1.1347x over previous
#include <cuda_runtime.h>
#include <cstdint>

static constexpr int NN = 50000;
static constexpr int EE = 600000;
static constexpr int GG = 64;
static constexpr int HH = 128;
static constexpr int TPB = 256;   // 8 warps: 4 in M (32 rows) x 2 in N (64 cols)

// ---------------- scratch (no allocations allowed) ----------------
__device__ int   d_row[EE];
__device__ int   d_col[EE];
__device__ int   d_batch[NN];
__device__ int   d_is64;
__device__ float d_e_sum[NN * HH];
__device__ float d_cnt[NN];
__device__ float d_e_mean[GG * HH];   // SUM accumulators
__device__ float d_v_mean[GG * HH];   // SUM accumulators
__device__ float d_gecnt[GG];
__device__ int   d_start[GG + 1];
__device__ float d_W1t[HH * 4 * HH];  // [N=128][K] transposed, tf32-rounded
__device__ float d_W2t[HH * HH];
__device__ float d_V1t[HH * 3 * HH];
__device__ float d_V2t[HH * HH];

// ---------------- helpers ----------------
__device__ __forceinline__ uint32_t smem_u32(const void* p) {
    uint32_t a;
    asm("{ .reg .u64 t; cvta.to.shared.u64 t, %1; cvt.u32.u64 %0, t; }" : "=r"(a) : "l"(p));
    return a;
}
__device__ __forceinline__ void ldsm4(uint32_t* r, uint32_t addr) {
    asm volatile("ldmatrix.sync.aligned.m8n8.x4.shared.b16 {%0,%1,%2,%3}, [%4];"
        : "=r"(r[0]), "=r"(r[1]), "=r"(r[2]), "=r"(r[3]) : "r"(addr));
}
__device__ __forceinline__ void mma_tf32(float* c, const uint32_t* a, uint32_t b0, uint32_t b1) {
    asm volatile("mma.sync.aligned.m16n8k8.row.col.f32.tf32.tf32.f32 "
        "{%0,%1,%2,%3}, {%4,%5,%6,%7}, {%8,%9}, {%0,%1,%2,%3};"
        : "+f"(c[0]), "+f"(c[1]), "+f"(c[2]), "+f"(c[3])
        : "r"(a[0]), "r"(a[1]), "r"(a[2]), "r"(a[3]), "r"(b0), "r"(b1));
}
__device__ __forceinline__ float tf32r(float v) {
    uint32_t r;
    asm("cvt.rna.tf32.f32 %0, %1;" : "=r"(r) : "f"(v));
    return __uint_as_float(r);
}
__device__ __forceinline__ float4 tf32r4s(float4 v, float s) {
    return make_float4(tf32r(v.x * s), tf32r(v.y * s), tf32r(v.z * s), tf32r(v.w * s));
}
__device__ __forceinline__ void cpa16(uint32_t dst, const void* src) {
    asm volatile("cp.async.cg.shared.global [%0], [%1], 16;" :: "r"(dst), "l"(src));
}
#define CP_COMMIT() asm volatile("cp.async.commit_group;" ::: "memory")
#define CP_WAIT0()  asm volatile("cp.async.wait_group 0;" ::: "memory")
__device__ __forceinline__ float softplusf(float v) {
    float t = __expf(-fabsf(v));
    return fmaxf(v, 0.0f) + __logf(1.0f + t);
}

// ---------------- prep kernels ----------------
__global__ void detect_kernel(const int* __restrict__ ei) {
    if (threadIdx.x == 0) {
        int all0 = 1;
        for (int i = 0; i < 64; ++i)
            if (ei[2 * i + 1] != 0) { all0 = 0; break; }
        d_is64 = all0;
    }
}
__global__ void convert_zero_kernel(const int* __restrict__ ei, const int* __restrict__ batch) {
    int i = blockIdx.x * 256 + threadIdx.x;
    int is64 = d_is64;
    if (i < EE) {
        d_row[i] = is64 ? ei[2 * i]          : ei[i];
        d_col[i] = is64 ? ei[2 * EE + 2 * i] : ei[EE + i];
    }
    if (i < NN) {
        d_batch[i] = is64 ? batch[2 * i] : batch[i];
        d_cnt[i] = 0.0f;
    }
    if (i < NN * HH) d_e_sum[i] = 0.0f;
    if (i < GG * HH) { d_e_mean[i] = 0.0f; d_v_mean[i] = 0.0f; }
    if (i < GG) d_gecnt[i] = 0.0f;
}
__global__ void prep_all_kernel(const float* __restrict__ We1, const float* __restrict__ We2,
                                const float* __restrict__ Wv1, const float* __restrict__ Wv2) {
    int i = blockIdx.x * 256 + threadIdx.x;
    if (i < 4 * HH * HH) {
        int k = i / HH, n = i % HH;
        d_W1t[n * (4 * HH) + k] = tf32r(We1[i]);
    }
    if (i < 3 * HH * HH) {
        int k = i / HH, n = i % HH;
        d_V1t[n * (3 * HH) + k] = tf32r(Wv1[i]);
    }
    if (i < HH * HH) {
        int k = i / HH, n = i % HH;
        d_W2t[n * HH + k] = tf32r(We2[i]);
        d_V2t[n * HH + k] = tf32r(Wv2[i]);
    }
}
__global__ void seg_starts_kernel() {
    int v = blockIdx.x * 256 + threadIdx.x;
    if (v >= NN) return;
    int b = d_batch[v];
    int bp = (v == 0) ? -1 : d_batch[v - 1];
    for (int g = bp + 1; g <= b; ++g) d_start[g] = v;
    if (v == NN - 1)
        for (int g = b + 1; g <= GG; ++g) d_start[g] = NN;
}

// ---------------- fused 2-layer MLP, mma.sync tf32, 4Mx2N warp tiling ----------------
// EDGE: in = [x[row], x[col], edge_attr, u[batch[row]]] (K=512), + scatter
// NODE: in = [x, e_sum*rc, u[batch]]                    (K=384)
// Dynamic smem (111104 B): base(2048) sRC(512) sA[2](20480) sB[2](20480) sH1(67584)
template<int NSEG, bool EDGE>
__global__ void __launch_bounds__(TPB, 2)
mlp2_mma(const float* __restrict__ s0, const float* __restrict__ s1,
         const float* __restrict__ s2, const float* __restrict__ s3,
         const float* __restrict__ W1t, const float* __restrict__ b1,
         const float* __restrict__ W2t, const float* __restrict__ b2,
         float* __restrict__ outp, int M)
{
    extern __shared__ char sm[];
    int* base = (int*)sm;
    float* sRC = (float*)(sm + 2048);
    char* sA0 = sm + 2560;
    char* sB0 = sm + 23040;
    char* sH1 = sm + 43520;
    const uint32_t aA = smem_u32(sA0), aB = smem_u32(sB0), aH1 = smem_u32(sH1);

    const int tid = threadIdx.x;
    const int w = tid >> 5, l = tid & 31;
    const int mg = w & 3, ng = w >> 2;          // 4 M-groups x 2 N-groups
    const int m0 = blockIdx.x * 128;

    if (tid < 128) {
        int r = m0 + tid;
        int b0 = 0, b1_ = 0, b2_ = 0, b3_ = 0;
        float rc = 1.0f;
        if (r < M) {
            if (EDGE) {
                int row = d_row[r];
                b0 = row * HH;
                b1_ = d_col[r] * HH;
                b2_ = r * HH;
                b3_ = d_batch[row] * HH;
            } else {
                b0 = r * HH;
                b1_ = r * HH;
                b2_ = d_batch[r] * HH;
                rc = 1.0f / fmaxf(d_cnt[r], 1.0f);
            }
        }
        base[tid * 4 + 0] = b0; base[tid * 4 + 1] = b1_;
        base[tid * 4 + 2] = b2_; base[tid * 4 + 3] = b3_;
        if (!EDGE) sRC[tid] = rc;
    }
    __syncthreads();

    const int row = tid >> 1, half = tid & 1;
    const int K1 = NSEG * 128;
    const int NCH = NSEG * 8;                 // even
    const uint32_t stg = (uint32_t)(row * 80 + half * 32);

    // ldmatrix lane offsets
    const uint32_t aoff0 = (uint32_t)((32 * mg + (l & 15)) * 80 + (l >> 4) * 16);
    const uint32_t aoff1 = aoff0 + 16 * 80;
    const uint32_t boffW = (uint32_t)(((l & 7) + ((l >> 4) & 1) * 8) * 80 + ((l >> 3) & 1) * 16
                                      + 64 * ng * 80);
    const uint32_t hoff0 = (uint32_t)((32 * mg + (l & 15)) * 528 + (l >> 4) * 16);
    const uint32_t hoff1 = hoff0 + 16 * 528;

    float acc[2][8][4];
    #pragma unroll
    for (int t = 0; t < 2; ++t)
        #pragma unroll
        for (int j = 0; j < 8; ++j)
            #pragma unroll
            for (int q = 0; q < 4; ++q) acc[t][j][q] = 0.0f;

    const float* sptr[4];
    sptr[0] = s0;
    sptr[1] = EDGE ? s1 : d_e_sum;
    sptr[2] = s2;
    sptr[3] = (NSEG == 4) ? s3 : s2;
    const float rcm = EDGE ? 1.0f : sRC[row];

    auto loadA = [&](int c, float4& g0, float4& g1) {
        int cc = (c < NCH) ? c : NCH - 1;
        int k0 = cc * 16;
        int sg = k0 >> 7;
        const float* ap = sptr[sg] + base[row * 4 + sg] + (k0 & 127) + half * 8;
        g0 = *(const float4*)ap;
        g1 = *(const float4*)(ap + 4);
    };
    auto segscale = [&](int c) -> float {
        return (!EDGE && ((c * 16) >> 7) == 1) ? rcm : 1.0f;
    };
    // one warp-chunk of MMAs from buffer at byte offset bo
    auto mmachunk = [&](uint32_t bo) {
        uint32_t a00[4], a01[4], a10[4], a11[4];
        ldsm4(a00, aA + bo + aoff0);
        ldsm4(a01, aA + bo + aoff0 + 32);
        ldsm4(a10, aA + bo + aoff1);
        ldsm4(a11, aA + bo + aoff1 + 32);
        #pragma unroll
        for (int p = 0; p < 4; ++p) {
            uint32_t b[4], b2[4];
            ldsm4(b,  aB + bo + boffW + p * 1280);        // n8 tiles 2p,2p+1, k8#0
            ldsm4(b2, aB + bo + boffW + p * 1280 + 32);   // k8#1
            mma_tf32(acc[0][2 * p],     a00, b[0],  b[1]);
            mma_tf32(acc[0][2 * p + 1], a00, b[2],  b[3]);
            mma_tf32(acc[1][2 * p],     a10, b[0],  b[1]);
            mma_tf32(acc[1][2 * p + 1], a10, b[2],  b[3]);
            mma_tf32(acc[0][2 * p],     a01, b2[0], b2[1]);
            mma_tf32(acc[0][2 * p + 1], a01, b2[2], b2[3]);
            mma_tf32(acc[1][2 * p],     a11, b2[0], b2[1]);
            mma_tf32(acc[1][2 * p + 1], a11, b2[2], b2[3]);
        }
    };

    // ---------------- layer 1 prologue ----------------
    float4 fA0, fA1, fB0, fB1;
    loadA(0, fA0, fA1);
    loadA(1, fB0, fB1);
    {
        const float* bp = W1t + row * K1 + half * 8;
        cpa16(aB + stg, bp);
        cpa16(aB + stg + 16, bp + 4);
        CP_COMMIT();
    }

    // ---------------- layer 1: unrolled by 2, 1 barrier per chunk ----------------
    #pragma unroll 1
    for (int c = 0; c < NCH; c += 2) {
        {   // sub-iter c (buffer 0)
            float sc = segscale(c);
            *(float4*)(sA0 + stg)      = tf32r4s(fA0, sc);
            *(float4*)(sA0 + stg + 16) = tf32r4s(fA1, sc);
            loadA(c + 2, fA0, fA1);
            CP_WAIT0();
            __syncthreads();
            {
                int k0n = ((c + 1) < NCH) ? (c + 1) * 16 : c * 16;
                const float* bp = W1t + row * K1 + k0n + half * 8;
                cpa16(aB + 10240 + stg, bp);
                cpa16(aB + 10240 + stg + 16, bp + 4);
            }
            CP_COMMIT();
            mmachunk(0);
        }
        {   // sub-iter c+1 (buffer 1)
            float sc = segscale(c + 1);
            *(float4*)(sA0 + 10240 + stg)      = tf32r4s(fB0, sc);
            *(float4*)(sA0 + 10240 + stg + 16) = tf32r4s(fB1, sc);
            loadA(c + 3, fB0, fB1);
            CP_WAIT0();
            __syncthreads();
            if (c + 2 < NCH) {
                const float* bp = W1t + row * K1 + (c + 2) * 16 + half * 8;
                cpa16(aB + stg, bp);
                cpa16(aB + stg + 16, bp + 4);
            }
            CP_COMMIT();
            mmachunk(10240);
        }
    }

    // W2(0) cp.async early
    {
        const float* bp = W2t + row * 128 + half * 8;
        cpa16(aB + stg, bp);
        cpa16(aB + stg + 16, bp + 4);
        CP_COMMIT();
    }

    // ---------------- layer-1 epilogue: bias + softplus -> sH1 ----------------
    #pragma unroll
    for (int t = 0; t < 2; ++t) {
        const int r0 = 32 * mg + 16 * t + (l >> 2);
        #pragma unroll
        for (int j = 0; j < 8; ++j) {
            int col = 64 * ng + j * 8 + 2 * (l & 3);
            float bb0 = __ldg(b1 + col), bb1 = __ldg(b1 + col + 1);
            float h00 = tf32r(softplusf(acc[t][j][0] + bb0));
            float h01 = tf32r(softplusf(acc[t][j][1] + bb1));
            float h10 = tf32r(softplusf(acc[t][j][2] + bb0));
            float h11 = tf32r(softplusf(acc[t][j][3] + bb1));
            *(float2*)(sH1 + r0 * 528 + col * 4)       = make_float2(h00, h01);
            *(float2*)(sH1 + (r0 + 8) * 528 + col * 4) = make_float2(h10, h11);
            acc[t][j][0] = acc[t][j][1] = acc[t][j][2] = acc[t][j][3] = 0.0f;
        }
    }

    // ---------------- layer 2: K=128, 8 chunks ----------------
    for (int c = 0; c < 8; ++c) {
        const uint32_t boffs = (uint32_t)((c & 1) * 10240);
        CP_WAIT0();
        __syncthreads();
        if (c + 1 < 8) {
            const float* bp = W2t + row * 128 + (c + 1) * 16 + half * 8;
            cpa16(aB + (boffs ^ 10240) + stg, bp);
            cpa16(aB + (boffs ^ 10240) + stg + 16, bp + 4);
        }
        CP_COMMIT();

        const int k0 = c * 16;
        uint32_t a00[4], a01[4], a10[4], a11[4];
        ldsm4(a00, aH1 + hoff0 + k0 * 4);
        ldsm4(a01, aH1 + hoff0 + k0 * 4 + 32);
        ldsm4(a10, aH1 + hoff1 + k0 * 4);
        ldsm4(a11, aH1 + hoff1 + k0 * 4 + 32);
        #pragma unroll
        for (int p = 0; p < 4; ++p) {
            uint32_t b[4], b2[4];
            ldsm4(b,  aB + boffs + boffW + p * 1280);
            ldsm4(b2, aB + boffs + boffW + p * 1280 + 32);
            mma_tf32(acc[0][2 * p],     a00, b[0],  b[1]);
            mma_tf32(acc[0][2 * p + 1], a00, b[2],  b[3]);
            mma_tf32(acc[1][2 * p],     a10, b[0],  b[1]);
            mma_tf32(acc[1][2 * p + 1], a10, b[2],  b[3]);
            mma_tf32(acc[0][2 * p],     a01, b2[0], b2[1]);
            mma_tf32(acc[0][2 * p + 1], a01, b2[2], b2[3]);
            mma_tf32(acc[1][2 * p],     a11, b2[0], b2[1]);
            mma_tf32(acc[1][2 * p + 1], a11, b2[2], b2[3]);
        }
    }

    // ---------------- epilogue 2: bias + softplus + store (+ scatter) ----------------
    #pragma unroll
    for (int t = 0; t < 2; ++t) {
        const int r0l = 32 * mg + 16 * t + (l >> 2);
        const int r0 = m0 + r0l;
        const int db0 = EDGE ? base[r0l * 4 + 0] : 0;
        const int db1 = EDGE ? base[(r0l + 8) * 4 + 0] : 0;
        #pragma unroll
        for (int j = 0; j < 8; ++j) {
            int col = 64 * ng + j * 8 + 2 * (l & 3);
            float bb0 = __ldg(b2 + col), bb1 = __ldg(b2 + col + 1);
            float o00 = softplusf(acc[t][j][0] + bb0);
            float o01 = softplusf(acc[t][j][1] + bb1);
            float o10 = softplusf(acc[t][j][2] + bb0);
            float o11 = softplusf(acc[t][j][3] + bb1);
            if (r0 < M) {
                *(float2*)(outp + (size_t)r0 * HH + col) = make_float2(o00, o01);
                if (EDGE) {
                    atomicAdd(&d_e_sum[db0 + col], o00);
                    atomicAdd(&d_e_sum[db0 + col + 1], o01);
                }
            }
            if (r0 + 8 < M) {
                *(float2*)(outp + (size_t)(r0 + 8) * HH + col) = make_float2(o10, o11);
                if (EDGE) {
                    atomicAdd(&d_e_sum[db1 + col], o10);
                    atomicAdd(&d_e_sum[db1 + col + 1], o11);
                }
            }
        }
        if (EDGE && ng == 0 && (l & 3) == 0) {   // rows shared by 2 warps: count once
            if (r0 < M)     atomicAdd(&d_cnt[db0 >> 7], 1.0f);
            if (r0 + 8 < M) atomicAdd(&d_cnt[db1 >> 7], 1.0f);
        }
    }
}

// ---------------- per-graph partial reductions (grid: GG x NSPLIT) ----------------
static constexpr int NSPLIT = 8;
__global__ void graph_partial_kernel(const float* __restrict__ xnew) {
    int g = blockIdx.x;
    int n = threadIdx.x;
    int s = d_start[g], e = d_start[g + 1];
    int len = e - s;
    int per = (len + NSPLIT - 1) / NSPLIT;
    int ls = s + blockIdx.y * per;
    int le = min(ls + per, e);
    if (ls >= le) return;
    float se = 0.0f, sv = 0.0f;
    for (int v = ls; v < le; ++v) {
        se += d_e_sum[v * HH + n];
        sv += xnew[(size_t)v * HH + n];
    }
    atomicAdd(&d_e_mean[g * HH + n], se);
    atomicAdd(&d_v_mean[g * HH + n], sv);
    __shared__ float red[HH];
    float sc = 0.0f;
    for (int v = ls + n; v < le; v += HH) sc += d_cnt[v];
    red[n] = sc;
    __syncthreads();
    for (int off = 64; off > 0; off >>= 1) {
        if (n < off) red[n] += red[n + off];
        __syncthreads();
    }
    if (n == 0) atomicAdd(&d_gecnt[g], red[0]);
}

__global__ void global_mlp_kernel(const float* __restrict__ u,
                                  const float* __restrict__ W1, const float* __restrict__ b1,
                                  const float* __restrict__ W2, const float* __restrict__ b2,
                                  float* __restrict__ out_u) {
    __shared__ float in[3 * HH];
    __shared__ float h1s[HH];
    int g = blockIdx.x, n = threadIdx.x;
    float ec = fmaxf(d_gecnt[g], 1.0f);
    float vc = fmaxf((float)(d_start[g + 1] - d_start[g]), 1.0f);
    in[n]          = u[g * HH + n];
    in[HH + n]     = d_e_mean[g * HH + n] / ec;
    in[2 * HH + n] = d_v_mean[g * HH + n] / vc;
    __syncthreads();
    float a = b1[n];
    for (int k = 0; k < 3 * HH; ++k) a += in[k] * W1[k * HH + n];
    h1s[n] = softplusf(a);
    __syncthreads();
    float o = b2[n];
    for (int k = 0; k < HH; ++k) o += h1s[k] * W2[k * HH + n];
    out_u[g * HH + n] = softplusf(o);
}

// ---------------- launch ----------------
extern "C" void kernel_launch(void* const* d_in, const int* in_sizes, int n_in,
                              void* d_out, int out_size) {
    const float* x     = (const float*)d_in[0];
    const int*   ei    = (const int*)d_in[1];
    const float* ea    = (const float*)d_in[2];
    const float* u     = (const float*)d_in[3];
    const int*   batch = (const int*)d_in[4];
    const float* We1 = (const float*)d_in[5];
    const float* be1 = (const float*)d_in[6];
    const float* We2 = (const float*)d_in[7];
    const float* be2 = (const float*)d_in[8];
    const float* Wv1 = (const float*)d_in[9];
    const float* bv1 = (const float*)d_in[10];
    const float* Wv2 = (const float*)d_in[11];
    const float* bv2 = (const float*)d_in[12];
    const float* Wu1 = (const float*)d_in[13];
    const float* bu1 = (const float*)d_in[14];
    const float* Wu2 = (const float*)d_in[15];
    const float* bu2 = (const float*)d_in[16];

    float* out   = (float*)d_out;
    float* out_x = out;
    float* out_e = out + (size_t)NN * HH;
    float* out_u = out + (size_t)(NN + EE) * HH;

    float *pW1t, *pW2t, *pV1t, *pV2t;
    cudaGetSymbolAddress((void**)&pW1t, d_W1t);
    cudaGetSymbolAddress((void**)&pW2t, d_W2t);
    cudaGetSymbolAddress((void**)&pV1t, d_V1t);
    cudaGetSymbolAddress((void**)&pV2t, d_V2t);

    const int SMEM = 111104;
    cudaFuncSetAttribute(mlp2_mma<4, true>,  cudaFuncAttributeMaxDynamicSharedMemorySize, SMEM);
    cudaFuncSetAttribute(mlp2_mma<3, false>, cudaFuncAttributeMaxDynamicSharedMemorySize, SMEM);

    detect_kernel<<<1, 32>>>(ei);
    convert_zero_kernel<<<(NN * HH + 255) / 256, 256>>>(ei, batch);
    prep_all_kernel<<<(4 * HH * HH + 255) / 256, 256>>>(We1, We2, Wv1, Wv2);

    // edge MLP + scatter (4th launch: ncu capture window)
    mlp2_mma<4, true><<<(EE + 127) / 128, TPB, SMEM>>>(
        x, x, ea, u, pW1t, be1, pW2t, be2, out_e, EE);

    // node MLP (e_aggr on the fly)
    mlp2_mma<3, false><<<(NN + 127) / 128, TPB, SMEM>>>(
        x, nullptr, u, nullptr, pV1t, bv1, pV2t, bv2, out_x, NN);

    seg_starts_kernel<<<(NN + 255) / 256, 256>>>();
    graph_partial_kernel<<<dim3(GG, NSPLIT), HH>>>(out_x);
    global_mlp_kernel<<<GG, HH>>>(u, Wu1, bu1, Wu2, bu2, out_u);
}